// round 15
// baseline (speedup 1.0000x reference)
#include <cuda_runtime.h>
#include <cuda_bf16.h>
#include <math.h>
#include <stdint.h>

#define NN   50000
#define EE   800000
#define ETOT (NN + EE)
#define IND  256
#define HIDD 72
#define NBLK ((NN + 255) / 256)   // 196

// ======================= warp-MMA helpers (baseline PTX) ====================
__device__ __forceinline__ uint32_t smem_to_u32(const void* p) {
    uint32_t a;
    asm("{ .reg .u64 t; cvta.to.shared.u64 t, %1; cvt.u32.u64 %0, t; }" : "=r"(a) : "l"(p));
    return a;
}
__device__ __forceinline__ void ldsm_x4(uint32_t* r, uint32_t addr) {
    asm volatile("ldmatrix.sync.aligned.m8n8.x4.shared.b16 {%0,%1,%2,%3}, [%4];"
        : "=r"(r[0]), "=r"(r[1]), "=r"(r[2]), "=r"(r[3]) : "r"(addr));
}
__device__ __forceinline__ void ldsm_x2(uint32_t* r, uint32_t addr) {
    asm volatile("ldmatrix.sync.aligned.m8n8.x2.shared.b16 {%0,%1}, [%2];"
        : "=r"(r[0]), "=r"(r[1]) : "r"(addr));
}
__device__ __forceinline__ void mma16816(float* c, const uint32_t* a, const uint32_t* b) {
    asm volatile("mma.sync.aligned.m16n8k16.row.col.f32.bf16.bf16.f32 "
        "{%0,%1,%2,%3}, {%4,%5,%6,%7}, {%8,%9}, {%0,%1,%2,%3};"
        : "+f"(c[0]), "+f"(c[1]), "+f"(c[2]), "+f"(c[3])
        : "r"(a[0]), "r"(a[1]), "r"(a[2]), "r"(a[3]), "r"(b[0]), "r"(b[1]));
}
__device__ __forceinline__ void cp16(uint32_t s, const void* g) {
    asm volatile("cp.async.cg.shared.global [%0], [%1], 16;" :: "r"(s), "l"(g));
}
#define CP_COMMIT() asm volatile("cp.async.commit_group;" ::: "memory")
#define CP_WAIT(n)  asm volatile("cp.async.wait_group %0;" :: "n"(n) : "memory")
// pack two fp32 -> bf16x2 (upper = first operand), RN rounding == __float2bfloat16
__device__ __forceinline__ uint32_t cvt_bf16x2(float hi, float lo) {
    uint32_t r;
    asm("cvt.rn.bf16x2.f32 %0, %1, %2;" : "=r"(r) : "f"(hi), "f"(lo));
    return r;
}

// ------------------------- scratch (device globals) -------------------------
__device__ __align__(16) int   g_rowptr[NN + 1];
__device__ __align__(16) int   g_blksum[NBLK];
__device__ __align__(16) int   g_cursor[NN];
__device__ __align__(16) int   g_csr[ETOT];
__device__ __align__(16) float g_x0[NN * HIDD];
__device__ __align__(16) float g_agg[NN * 288];
__device__ __align__(16) float g_o1[NN * 288];
__device__ __align__(16) float g_h2[NN * HIDD];
__device__ __align__(16) float g_o2[NN * HIDD];
__device__ __align__(16) float g_h3[NN * HIDD];
__device__ __align__(16) float g_ls1[NN * 4];
__device__ __align__(16) float g_ld1[NN * 4];
__device__ __align__(16) float g_ls2[NN];
__device__ __align__(16) float g_ld2[NN];
__device__ __align__(16) float g_ls3[NN];
__device__ __align__(16) float g_ld3[NN];
__device__ __align__(16) float g_cvec[8 * 72];
// per-layer transposed hi/lo weights [N, Kp]
__device__ __align__(16) __nv_bfloat16 g_w0h[72 * 256],  g_w0l[72 * 256];
__device__ __align__(16) __nv_bfloat16 g_w1h[288 * 96],  g_w1l[288 * 96];
__device__ __align__(16) __nv_bfloat16 g_w2h[72 * 288],  g_w2l[72 * 288];
__device__ __align__(16) __nv_bfloat16 g_w3h[72 * 96],   g_w3l[72 * 96];

// ------------------------------ CSR build ----------------------------------
__global__ void k_count_deg(const int* __restrict__ ei) {
    int e = blockIdx.x * blockDim.x + threadIdx.x;
    if (e < EE) atomicAdd(&g_rowptr[ei[EE + e]], 1);
}
// per-block exclusive scan of (deg_e + 1); block total -> g_blksum
__global__ void __launch_bounds__(256) k_scan_blk() {
    __shared__ int wsum[8];
    int tid = threadIdx.x, lane = tid & 31, wid = tid >> 5;
    int idx = blockIdx.x * 256 + tid;
    int v = (idx < NN) ? g_rowptr[idx] + 1 : 0;   // +1 = self loop, folded
    int x = v;
    #pragma unroll
    for (int o = 1; o < 32; o <<= 1) {
        int y = __shfl_up_sync(0xffffffffu, x, o);
        if (lane >= o) x += y;
    }
    if (lane == 31) wsum[wid] = x;
    __syncthreads();
    if (wid == 0 && lane < 8) {
        int s = wsum[lane];
        #pragma unroll
        for (int o = 1; o < 8; o <<= 1) {
            int y = __shfl_up_sync(0x000000ffu, s, o);
            if (lane >= o) s += y;
        }
        wsum[lane] = s;
    }
    __syncthreads();
    int excl = (wid ? wsum[wid - 1] : 0) + x - v;
    if (idx < NN) g_rowptr[idx] = excl;
    if (tid == 0) g_blksum[blockIdx.x] = wsum[7];
}
__global__ void __launch_bounds__(256) k_scan_top() {
    __shared__ int wsum[8];
    int tid = threadIdx.x, lane = tid & 31, wid = tid >> 5;
    int v = (tid < NBLK) ? g_blksum[tid] : 0;
    int x = v;
    #pragma unroll
    for (int o = 1; o < 32; o <<= 1) {
        int y = __shfl_up_sync(0xffffffffu, x, o);
        if (lane >= o) x += y;
    }
    if (lane == 31) wsum[wid] = x;
    __syncthreads();
    if (wid == 0 && lane < 8) {
        int s = wsum[lane];
        #pragma unroll
        for (int o = 1; o < 8; o <<= 1) {
            int y = __shfl_up_sync(0x000000ffu, s, o);
            if (lane >= o) s += y;
        }
        wsum[lane] = s;
    }
    __syncthreads();
    int excl = (wid ? wsum[wid - 1] : 0) + x - v;
    if (tid < NBLK) g_blksum[tid] = excl;
}
__global__ void k_add_self() {
    int i = blockIdx.x * blockDim.x + threadIdx.x;
    if (i < NN) {
        int r = g_rowptr[i] + g_blksum[i >> 8];
        g_rowptr[i] = r;
        g_csr[r] = i;
        g_cursor[i] = r + 1;
    }
    if (i == 0) g_rowptr[NN] = ETOT;
}
__global__ void k_scatter(const int* __restrict__ ei) {
    int e = blockIdx.x * blockDim.x + threadIdx.x;
    if (e < EE) {
        int s = ei[e];
        int d = ei[EE + e];
        int pos = atomicAdd(&g_cursor[d], 1);
        g_csr[pos] = s;
    }
}

// --------------- one-shot prep: all weight hi/lo transposes + cvec -----------
__device__ __forceinline__ void cvt1(const float* W, __nv_bfloat16* H, __nv_bfloat16* L,
                                     int e, int K, int N, int Kp) {
    int n = e / Kp, k = e - n * Kp;
    float v = (k < K) ? W[(size_t)k * N + n] : 0.f;
    __nv_bfloat16 h = __float2bfloat16(v);
    H[e] = h;
    L[e] = __float2bfloat16(v - __bfloat162float(h));
}
__global__ void k_prep(const float* __restrict__ W_in, const float* __restrict__ W1,
                       const float* __restrict__ W2, const float* __restrict__ W3,
                       const float* __restrict__ as1, const float* __restrict__ ad1)
{
    int idx = blockIdx.x * blockDim.x + threadIdx.x;
    if (idx < 18432) {
        cvt1(W_in, g_w0h, g_w0l, idx, 256, 72, 256);
    } else if (idx < 46080) {
        cvt1(W1, g_w1h, g_w1l, idx - 18432, 72, 288, 96);
    } else if (idx < 66816) {
        cvt1(W2, g_w2h, g_w2l, idx - 46080, 288, 72, 288);
    } else if (idx < 73728) {
        cvt1(W3, g_w3h, g_w3l, idx - 66816, 72, 72, 96);
    } else if (idx < 74304) {
        int t = idx - 73728;
        int which = t / 288;
        int r = t % 288;
        int h = r / 72, k = r % 72;
        const float* a = (which ? ad1 : as1) + h * 72;
        const float* wrow = W1 + (size_t)k * 288 + h * 72;
        float s = 0.f;
        #pragma unroll 8
        for (int c = 0; c < 72; c++) s += wrow[c] * a[c];
        g_cvec[t] = s;
    }
}

// ---- layer-1 logits straight from x0 (cvec identity) ------------------------
__global__ void __launch_bounds__(256) k_logits8(
    const float* __restrict__ x0, float* __restrict__ ls, float* __restrict__ ld)
{
    __shared__ float cs[288], cd[288];
    for (int i = threadIdx.x; i < 288; i += 256) {
        cs[i] = g_cvec[i];
        cd[i] = g_cvec[288 + i];
    }
    __syncthreads();
    int n = blockIdx.x * blockDim.x + threadIdx.x;
    if (n >= NN) return;
    const float* row = x0 + (size_t)n * 72;
    float s[4] = {0.f, 0.f, 0.f, 0.f}, d[4] = {0.f, 0.f, 0.f, 0.f};
    for (int k = 0; k < 72; k += 4) {
        float4 v = *(const float4*)(row + k);
        #pragma unroll
        for (int h = 0; h < 4; h++) {
            float4 a = *(const float4*)(cs + h * 72 + k);
            float4 b = *(const float4*)(cd + h * 72 + k);
            s[h] += v.x * a.x + v.y * a.y + v.z * a.z + v.w * a.w;
            d[h] += v.x * b.x + v.y * b.y + v.z * b.z + v.w * b.w;
        }
    }
    *(float4*)(ls + (size_t)n * 4) = make_float4(s[0], s[1], s[2], s[3]);
    *(float4*)(ld + (size_t)n * 4) = make_float4(d[0], d[1], d[2], d[3]);
}

// -------------------- pipelined mma.sync GEMM (round-7/11 form) --------------
#define PITCH 40
#define BPART (72 * PITCH * 2)

__global__ void __launch_bounds__(384, 2)
k_mmagemm(const float* __restrict__ A, int aStride, int aColShift,
          const __nv_bfloat16* __restrict__ Bh, const __nv_bfloat16* __restrict__ Bl,
          const float* __restrict__ bias, float* __restrict__ C,
          const float* __restrict__ asrc, const float* __restrict__ adst,
          float* __restrict__ ls, float* __restrict__ ld, int lstride,
          int M, int Kin, int KoutTot, int useBias, int actELU)
{
    __shared__ __nv_bfloat16 sAh[128 * PITCH];
    __shared__ __nv_bfloat16 sAl[128 * PITCH];
    __shared__ __nv_bfloat16 sB[2][2][72 * PITCH];
    __shared__ float sLs[128];
    __shared__ float sLd[128];

    int tid = threadIdx.x, wid = tid >> 5, lane = tid & 31;
    int warpM = wid & 3;
    int warpN = wid >> 2;
    int r0 = blockIdx.x * 128;
    int c0 = blockIdx.y * 72;
    int Kp = (Kin + 31) & ~31;
    int aBase = aColShift ? c0 : 0;
    const int chunks = Kp >> 5;

    float acc[2][3][4];
    #pragma unroll
    for (int mi = 0; mi < 2; mi++)
        #pragma unroll
        for (int ni = 0; ni < 3; ni++)
            #pragma unroll
            for (int q = 0; q < 4; q++) acc[mi][ni][q] = 0.f;

    uint32_t uAh = smem_to_u32(sAh), uAl = smem_to_u32(sAl);
    uint32_t uB  = smem_to_u32(sB);

    int lm = lane >> 3, lj = lane & 7;
    uint32_t aoffA = (uint32_t)(warpM * 32 + (lm & 1) * 8 + lj) * (PITCH * 2) + (lm >> 1) * 16;
    uint32_t aoffB = (uint32_t)(warpN * 24 + lj) * (PITCH * 2) + (lm & 1) * 16;

    auto loadA4 = [&](int idx, int kbase) -> float4 {
        int row = idx >> 3, seg = idx & 7;
        int gr = r0 + row;
        int gc = kbase + seg * 4;
        float4 v = make_float4(0.f, 0.f, 0.f, 0.f);
        if (gr < M) {
            const float* ap = A + (size_t)gr * aStride + aBase;
            if (gc + 3 < Kin) v = *(const float4*)(ap + gc);
            else {
                if (gc + 0 < Kin) v.x = ap[gc + 0];
                if (gc + 1 < Kin) v.y = ap[gc + 1];
                if (gc + 2 < Kin) v.z = ap[gc + 2];
                if (gc + 3 < Kin) v.w = ap[gc + 3];
            }
        }
        return v;
    };
    // packed bf16x2 hi/lo split: same RN rounding, half the convert/STS issue
    auto storeA4 = [&](int idx, float4 v) {
        int row = idx >> 3, seg = idx & 7;
        uint32_t h01 = cvt_bf16x2(v.y, v.x);
        uint32_t h23 = cvt_bf16x2(v.w, v.z);
        float hx = __uint_as_float(h01 << 16);
        float hy = __uint_as_float(h01 & 0xffff0000u);
        float hz = __uint_as_float(h23 << 16);
        float hw = __uint_as_float(h23 & 0xffff0000u);
        uint32_t l01 = cvt_bf16x2(v.y - hy, v.x - hx);
        uint32_t l23 = cvt_bf16x2(v.w - hw, v.z - hz);
        *(uint2*)(sAh + row * PITCH + seg * 4) = make_uint2(h01, h23);
        *(uint2*)(sAl + row * PITCH + seg * 4) = make_uint2(l01, l23);
    };
    auto stageB = [&](int ch) {
        int kbase = ch << 5;
        int buf = ch & 1;
        #pragma unroll
        for (int rep = 0; rep < 2; rep++) {
            int idx = tid + rep * 384;
            if (idx < 576) {
                int part = (idx >= 288);
                int e = part ? idx - 288 : idx;
                int r = e >> 2, seg = e & 3;
                const __nv_bfloat16* gp =
                    (part ? Bl : Bh) + (size_t)(c0 + r) * Kp + kbase + seg * 8;
                uint32_t sp = uB + (uint32_t)(buf * 2 + part) * BPART
                                 + (uint32_t)r * (PITCH * 2) + seg * 16;
                cp16(sp, gp);
            }
        }
    };

    // ---- prologue ----
    stageB(0);
    CP_COMMIT();
    float4 aReg0 = loadA4(tid, 0);
    float4 aReg1 = loadA4(tid + 384, 0);
    float4 aReg2 = (tid < 256) ? loadA4(tid + 768, 0) : make_float4(0.f, 0.f, 0.f, 0.f);

    for (int ch = 0; ch < chunks; ch++) {
        storeA4(tid, aReg0);
        storeA4(tid + 384, aReg1);
        if (tid < 256) storeA4(tid + 768, aReg2);

        bool more = (ch + 1 < chunks);
        if (more) {
            int kb = (ch + 1) << 5;
            aReg0 = loadA4(tid, kb);
            aReg1 = loadA4(tid + 384, kb);
            if (tid < 256) aReg2 = loadA4(tid + 768, kb);
            stageB(ch + 1);
            CP_COMMIT();
            CP_WAIT(1);
        } else {
            CP_WAIT(0);
        }
        __syncthreads();

        uint32_t bufOff = (uint32_t)(ch & 1) * 2 * BPART;
        #pragma unroll
        for (int ks = 0; ks < 2; ks++) {
            uint32_t kb = ks * 32;
            uint32_t fah[2][4], fal[2][4], fbh[3][2], fbl[3][2];
            #pragma unroll
            for (int mi = 0; mi < 2; mi++) {
                uint32_t off = aoffA + (uint32_t)mi * 16 * (PITCH * 2) + kb;
                ldsm_x4(fah[mi], uAh + off);
                ldsm_x4(fal[mi], uAl + off);
            }
            #pragma unroll
            for (int ni = 0; ni < 3; ni++) {
                uint32_t off = aoffB + (uint32_t)ni * 8 * (PITCH * 2) + kb;
                ldsm_x2(fbh[ni], uB + bufOff + off);
                ldsm_x2(fbl[ni], uB + bufOff + BPART + off);
            }
            #pragma unroll
            for (int mi = 0; mi < 2; mi++)
                #pragma unroll
                for (int ni = 0; ni < 3; ni++) {
                    mma16816(acc[mi][ni], fah[mi], fbh[ni]);
                    mma16816(acc[mi][ni], fal[mi], fbh[ni]);
                    mma16816(acc[mi][ni], fah[mi], fbl[ni]);
                }
        }
        __syncthreads();
    }

    // ---- store C (+bias, +ELU) ----
    int rb = r0 + warpM * 32 + (lane >> 2);
    int cb = c0 + warpN * 24 + (lane & 3) * 2;
    #pragma unroll
    for (int mi = 0; mi < 2; mi++) {
        #pragma unroll
        for (int ni = 0; ni < 3; ni++) {
            int r = rb + mi * 16;
            int c = cb + ni * 8;
            float2 v0 = make_float2(acc[mi][ni][0], acc[mi][ni][1]);
            float2 v1 = make_float2(acc[mi][ni][2], acc[mi][ni][3]);
            if (useBias) {
                float bx = __ldg(bias + c), by = __ldg(bias + c + 1);
                v0.x += bx; v0.y += by;
                v1.x += bx; v1.y += by;
            }
            if (actELU) {
                v0.x = (v0.x > 0.f) ? v0.x : expm1f(v0.x);
                v0.y = (v0.y > 0.f) ? v0.y : expm1f(v0.y);
                v1.x = (v1.x > 0.f) ? v1.x : expm1f(v1.x);
                v1.y = (v1.y > 0.f) ? v1.y : expm1f(v1.y);
            }
            if (r < M)     *(float2*)(C + (size_t)r * KoutTot + c) = v0;
            if (r + 8 < M) *(float2*)(C + (size_t)(r + 8) * KoutTot + c) = v1;
        }
    }

    // ---- fused attention logits (single head; layers 2/3) ----
    if (ls != nullptr) {
        const float* av = asrc + blockIdx.y * 72;
        const float* dv = adst + blockIdx.y * 72;
        float as6[6], ad6[6];
        #pragma unroll
        for (int t6 = 0; t6 < 6; t6++) {
            int ni = t6 >> 1, j = t6 & 1;
            int cc = warpN * 24 + ni * 8 + (lane & 3) * 2 + j;
            as6[t6] = __ldg(av + cc);
            ad6[t6] = __ldg(dv + cc);
        }
        float sp[4], dp[4];
        #pragma unroll
        for (int mi = 0; mi < 2; mi++)
            #pragma unroll
            for (int half = 0; half < 2; half++) {
                float s = 0.f, d = 0.f;
                #pragma unroll
                for (int ni = 0; ni < 3; ni++) {
                    s += acc[mi][ni][half * 2 + 0] * as6[ni * 2 + 0];
                    s += acc[mi][ni][half * 2 + 1] * as6[ni * 2 + 1];
                    d += acc[mi][ni][half * 2 + 0] * ad6[ni * 2 + 0];
                    d += acc[mi][ni][half * 2 + 1] * ad6[ni * 2 + 1];
                }
                sp[mi * 2 + half] = s;
                dp[mi * 2 + half] = d;
            }
        #pragma unroll
        for (int k = 0; k < 4; k++) {
            #pragma unroll
            for (int o = 1; o < 4; o <<= 1) {
                sp[k] += __shfl_xor_sync(0xffffffffu, sp[k], o);
                dp[k] += __shfl_xor_sync(0xffffffffu, dp[k], o);
            }
        }
        if (tid < 128) { sLs[tid] = 0.f; sLd[tid] = 0.f; }
        __syncthreads();
        if ((lane & 3) == 0) {
            int rloc = warpM * 32 + (lane >> 2);
            atomicAdd(&sLs[rloc],      sp[0]); atomicAdd(&sLd[rloc],      dp[0]);
            atomicAdd(&sLs[rloc + 8],  sp[1]); atomicAdd(&sLd[rloc + 8],  dp[1]);
            atomicAdd(&sLs[rloc + 16], sp[2]); atomicAdd(&sLd[rloc + 16], dp[2]);
            atomicAdd(&sLs[rloc + 24], sp[3]); atomicAdd(&sLd[rloc + 24], dp[3]);
        }
        __syncthreads();
        if (tid < 128) {
            int gr = r0 + tid;
            if (gr < M) {
                ls[(size_t)gr * lstride + blockIdx.y] = sLs[tid];
                ld[(size_t)gr * lstride + blockIdx.y] = sLd[tid];
            }
        }
    }
}

// ------- layer-1 edge pass: aggregate x0 (72 cols) under 4 head alphas -------
__global__ void __launch_bounds__(256) k_edge4agg(
    const float* __restrict__ x0, const float* __restrict__ ls,
    const float* __restrict__ ld, float* __restrict__ agg)
{
    int node = (blockIdx.x * blockDim.x + threadIdx.x) >> 5;
    if (node >= NN) return;
    int lane = threadIdx.x & 31;
    int s0 = g_rowptr[node], s1 = g_rowptr[node + 1];

    float4 ldv = __ldg((const float4*)ld + node);
    bool act = (lane < 18);

    float4 a0 = make_float4(0.f, 0.f, 0.f, 0.f);
    float4 a1 = a0, a2 = a0, a3 = a0;
    float  sum0 = 0.f, sum1 = 0.f, sum2 = 0.f, sum3 = 0.f;

    #pragma unroll 8
    for (int i = s0; i < s1; i++) {
        int s = g_csr[i];
        float4 lv = __ldg((const float4*)ls + s);
        float v0 = lv.x + ldv.x; v0 = fmaxf(v0, 0.2f * v0);
        float v1 = lv.y + ldv.y; v1 = fmaxf(v1, 0.2f * v1);
        float v2 = lv.z + ldv.z; v2 = fmaxf(v2, 0.2f * v2);
        float v3 = lv.w + ldv.w; v3 = fmaxf(v3, 0.2f * v3);
        float p0 = __expf(v0), p1 = __expf(v1);
        float p2 = __expf(v2), p3 = __expf(v3);
        sum0 += p0; sum1 += p1; sum2 += p2; sum3 += p3;

        if (act) {
            float4 v = __ldg((const float4*)(x0 + (size_t)s * 72) + lane);
            a0.x += p0 * v.x; a0.y += p0 * v.y; a0.z += p0 * v.z; a0.w += p0 * v.w;
            a1.x += p1 * v.x; a1.y += p1 * v.y; a1.z += p1 * v.z; a1.w += p1 * v.w;
            a2.x += p2 * v.x; a2.y += p2 * v.y; a2.z += p2 * v.z; a2.w += p2 * v.w;
            a3.x += p3 * v.x; a3.y += p3 * v.y; a3.z += p3 * v.z; a3.w += p3 * v.w;
        }
    }

    if (act) {
        float i0 = 1.f / fmaxf(sum0, 1e-16f);
        float i1 = 1.f / fmaxf(sum1, 1e-16f);
        float i2 = 1.f / fmaxf(sum2, 1e-16f);
        float i3 = 1.f / fmaxf(sum3, 1e-16f);
        float* o = agg + (size_t)node * 288 + lane * 4;
        *(float4*)(o)       = make_float4(a0.x * i0, a0.y * i0, a0.z * i0, a0.w * i0);
        *(float4*)(o + 72)  = make_float4(a1.x * i1, a1.y * i1, a1.z * i1, a1.w * i1);
        *(float4*)(o + 144) = make_float4(a2.x * i2, a2.y * i2, a2.z * i2, a2.w * i2);
        *(float4*)(o + 216) = make_float4(a3.x * i3, a3.y * i3, a3.z * i3, a3.w * i3);
    }
}

// --------------- single-head edge pass (layer 2), float4 gather ---------------
__global__ void __launch_bounds__(256) k_edge1(
    const float* __restrict__ hfeat, const float* __restrict__ ls,
    const float* __restrict__ ld, const float* __restrict__ bias,
    float* __restrict__ outp)
{
    int node = (blockIdx.x * blockDim.x + threadIdx.x) >> 5;
    if (node >= NN) return;
    int lane = threadIdx.x & 31;
    int s0 = g_rowptr[node], s1 = g_rowptr[node + 1];

    float ldv = __ldg(ld + node);
    bool act = (lane < 18);
    float4 acc = make_float4(0.f, 0.f, 0.f, 0.f);
    float  sum = 0.f;

    #pragma unroll 8
    for (int i = s0; i < s1; i++) {
        int s = g_csr[i];
        float v = __ldg(ls + s) + ldv;
        v = fmaxf(v, 0.2f * v);
        float p = __expf(v);
        sum += p;
        if (act) {
            float4 h = __ldg((const float4*)(hfeat + (size_t)s * 72) + lane);
            acc.x += p * h.x; acc.y += p * h.y;
            acc.z += p * h.z; acc.w += p * h.w;
        }
    }

    if (act) {
        float inv = 1.f / fmaxf(sum, 1e-16f);
        int c = lane * 4;
        float4 b = __ldg((const float4*)(bias + c));
        float4 r;
        r.x = acc.x * inv + b.x; r.x = (r.x > 0.f) ? r.x : expm1f(r.x);
        r.y = acc.y * inv + b.y; r.y = (r.y > 0.f) ? r.y : expm1f(r.y);
        r.z = acc.z * inv + b.z; r.z = (r.z > 0.f) ? r.z : expm1f(r.z);
        r.w = acc.w * inv + b.w; r.w = (r.w > 0.f) ? r.w : expm1f(r.w);
        *(float4*)(outp + (size_t)node * 72 + c) = r;
    }
}

// ---- layer-3 edge pass fused with residual + score MLP (final output) -------
__global__ void __launch_bounds__(256) k_edge1f(
    const float* __restrict__ hfeat, const float* __restrict__ ls,
    const float* __restrict__ ld, const float* __restrict__ bias,
    const float* __restrict__ x0,
    const float* __restrict__ Ws1, const float* __restrict__ bs1,
    const float* __restrict__ Ws2, const float* __restrict__ bs2,
    float* __restrict__ out)
{
    __shared__ float w1s[72 * 32];
    __shared__ float w2s[32];
    __shared__ float b1s[32];
    __shared__ float b2s;
    __shared__ __align__(16) float vbuf[8][72];

    for (int i = threadIdx.x; i < 72 * 32; i += 256) w1s[i] = Ws1[i];
    if (threadIdx.x < 32) {
        w2s[threadIdx.x] = Ws2[threadIdx.x];
        b1s[threadIdx.x] = bs1[threadIdx.x];
    }
    if (threadIdx.x == 0) b2s = bs2[0];
    __syncthreads();

    int node = (blockIdx.x * blockDim.x + threadIdx.x) >> 5;
    if (node >= NN) return;
    int lane = threadIdx.x & 31;
    int warp = threadIdx.x >> 5;
    int s0 = g_rowptr[node], s1 = g_rowptr[node + 1];

    float ldv = __ldg(ld + node);
    bool act = (lane < 18);
    float4 acc = make_float4(0.f, 0.f, 0.f, 0.f);
    float  sum = 0.f;

    #pragma unroll 8
    for (int i = s0; i < s1; i++) {
        int s = g_csr[i];
        float v = __ldg(ls + s) + ldv;
        v = fmaxf(v, 0.2f * v);
        float p = __expf(v);
        sum += p;
        if (act) {
            float4 h = __ldg((const float4*)(hfeat + (size_t)s * 72) + lane);
            acc.x += p * h.x; acc.y += p * h.y;
            acc.z += p * h.z; acc.w += p * h.w;
        }
    }

    if (act) {
        float inv = 1.f / fmaxf(sum, 1e-16f);
        int c = lane * 4;
        float4 b = __ldg((const float4*)(bias + c));
        float4 xv = __ldg((const float4*)(x0 + (size_t)node * 72) + lane);
        float4 r;
        r.x = acc.x * inv + b.x; r.x = ((r.x > 0.f) ? r.x : expm1f(r.x)) + xv.x;
        r.y = acc.y * inv + b.y; r.y = ((r.y > 0.f) ? r.y : expm1f(r.y)) + xv.y;
        r.z = acc.z * inv + b.z; r.z = ((r.z > 0.f) ? r.z : expm1f(r.z)) + xv.z;
        r.w = acc.w * inv + b.w; r.w = ((r.w > 0.f) ? r.w : expm1f(r.w)) + xv.w;
        *(float4*)(&vbuf[warp][c]) = r;
    }
    __syncwarp();

    // score MLP: lane j owns hidden unit j
    float t = b1s[lane];
    #pragma unroll 8
    for (int k = 0; k < 72; k++) t += vbuf[warp][k] * w1s[k * 32 + lane];
    float sc = fmaxf(t, 0.f) * w2s[lane];
    #pragma unroll
    for (int o = 16; o > 0; o >>= 1) sc += __shfl_xor_sync(0xffffffffu, sc, o);
    if (lane == 0) out[node] = sc + b2s;
}

// ------------------------------ launch ---------------------------------------
extern "C" void kernel_launch(void* const* d_in, const int* in_sizes, int n_in,
                              void* d_out, int out_size)
{
    const float* x    = (const float*)d_in[0];
    const int*   ei   = (const int*)d_in[1];
    const float* W_in = (const float*)d_in[2];
    const float* b_in = (const float*)d_in[3];
    const float* W1   = (const float*)d_in[4];
    const float* as1  = (const float*)d_in[5];
    const float* ad1  = (const float*)d_in[6];
    const float* b1   = (const float*)d_in[7];
    const float* W2   = (const float*)d_in[8];
    const float* as2  = (const float*)d_in[9];
    const float* ad2  = (const float*)d_in[10];
    const float* b2   = (const float*)d_in[11];
    const float* W3   = (const float*)d_in[12];
    const float* as3  = (const float*)d_in[13];
    const float* ad3  = (const float*)d_in[14];
    const float* b3   = (const float*)d_in[15];
    const float* Ws1  = (const float*)d_in[16];
    const float* bs1  = (const float*)d_in[17];
    const float* Ws2  = (const float*)d_in[18];
    const float* bs2  = (const float*)d_in[19];
    float* out = (float*)d_out;

    float *px0, *pagg, *po1, *ph2, *po2, *ph3;
    float *pls1, *pld1, *pls2, *pld2, *pls3, *pld3;
    int* prowptr;
    __nv_bfloat16 *pw0h, *pw0l, *pw1h, *pw1l, *pw2h, *pw2l, *pw3h, *pw3l;
    cudaGetSymbolAddress((void**)&px0,  g_x0);
    cudaGetSymbolAddress((void**)&pagg, g_agg);
    cudaGetSymbolAddress((void**)&po1,  g_o1);
    cudaGetSymbolAddress((void**)&ph2,  g_h2);
    cudaGetSymbolAddress((void**)&po2,  g_o2);
    cudaGetSymbolAddress((void**)&ph3,  g_h3);
    cudaGetSymbolAddress((void**)&pls1, g_ls1);
    cudaGetSymbolAddress((void**)&pld1, g_ld1);
    cudaGetSymbolAddress((void**)&pls2, g_ls2);
    cudaGetSymbolAddress((void**)&pld2, g_ld2);
    cudaGetSymbolAddress((void**)&pls3, g_ls3);
    cudaGetSymbolAddress((void**)&pld3, g_ld3);
    cudaGetSymbolAddress((void**)&prowptr, g_rowptr);
    cudaGetSymbolAddress((void**)&pw0h, g_w0h);
    cudaGetSymbolAddress((void**)&pw0l, g_w0l);
    cudaGetSymbolAddress((void**)&pw1h, g_w1h);
    cudaGetSymbolAddress((void**)&pw1l, g_w1l);
    cudaGetSymbolAddress((void**)&pw2h, g_w2h);
    cudaGetSymbolAddress((void**)&pw2l, g_w2l);
    cudaGetSymbolAddress((void**)&pw3h, g_w3h);
    cudaGetSymbolAddress((void**)&pw3l, g_w3l);

    // side stream + fork/join events (capture-safe: branches recorded into graph)
    cudaStream_t side;
    cudaStreamCreateWithFlags(&side, cudaStreamNonBlocking);
    cudaEvent_t eFork, eJoin;
    cudaEventCreateWithFlags(&eFork, cudaEventDisableTiming);
    cudaEventCreateWithFlags(&eJoin, cudaEventDisableTiming);

    // fork: CSR build runs concurrently with layer-0 compute
    cudaEventRecord(eFork, 0);
    cudaStreamWaitEvent(side, eFork, 0);

    // --- side branch: CSR build ---
    cudaMemsetAsync(prowptr, 0, (NN + 1) * sizeof(int), side);
    k_count_deg<<<(EE + 255) / 256, 256, 0, side>>>(ei);
    k_scan_blk<<<NBLK, 256, 0, side>>>();
    k_scan_top<<<1, 256, 0, side>>>();
    k_add_self<<<(NN + 255) / 256, 256, 0, side>>>();
    k_scatter<<<(EE + 255) / 256, 256, 0, side>>>(ei);
    cudaEventRecord(eJoin, side);

    // --- main branch: prep + layer-0 GEMM + layer-1 logits ---
    k_prep<<<(74304 + 255) / 256, 256>>>(W_in, W1, W2, W3, as1, ad1);
    k_mmagemm<<<dim3(391, 1), 384>>>(x, 256, 0, pw0h, pw0l, b_in, px0,
                                     nullptr, nullptr, nullptr, nullptr, 1,
                                     NN, 256, 72, 1, 0);
    k_logits8<<<(NN + 255) / 256, 256>>>(px0, pls1, pld1);

    // join: edge aggregation needs both CSR and logits
    cudaStreamWaitEvent(0, eJoin, 0);

    // --- layer 1 ---
    k_edge4agg<<<(NN * 32) / 256, 256>>>(px0, pls1, pld1, pagg);
    k_mmagemm<<<dim3(391, 4), 384>>>(pagg, 288, 1, pw1h, pw1l, b1, po1,
                                     nullptr, nullptr, nullptr, nullptr, 1,
                                     NN, 72, 288, 1, 1);

    // --- layer 2 ---
    k_mmagemm<<<dim3(391, 1), 384>>>(po1, 288, 0, pw2h, pw2l, nullptr, ph2,
                                     as2, ad2, pls2, pld2, 1,
                                     NN, 288, 72, 0, 0);
    k_edge1<<<(NN * 32) / 256, 256>>>(ph2, pls2, pld2, b2, po2);

    // --- layer 3 ---
    k_mmagemm<<<dim3(391, 1), 384>>>(po2, 72, 0, pw3h, pw3l, nullptr, ph3,
                                     as3, ad3, pls3, pld3, 1,
                                     NN, 72, 72, 0, 0);
    k_edge1f<<<(NN * 32) / 256, 256>>>(ph3, pls3, pld3, b3, px0,
                                       Ws1, bs1, Ws2, bs2, out);
}

// round 16
// speedup vs baseline: 1.0645x; 1.0645x over previous
#include <cuda_runtime.h>
#include <cuda_bf16.h>
#include <math.h>
#include <stdint.h>

#define NN   50000
#define EE   800000
#define ETOT (NN + EE)
#define IND  256
#define HIDD 72
#define NBLK ((NN + 255) / 256)   // 196

// ======================= warp-MMA helpers (baseline PTX) ====================
__device__ __forceinline__ uint32_t smem_to_u32(const void* p) {
    uint32_t a;
    asm("{ .reg .u64 t; cvta.to.shared.u64 t, %1; cvt.u32.u64 %0, t; }" : "=r"(a) : "l"(p));
    return a;
}
__device__ __forceinline__ void ldsm_x4(uint32_t* r, uint32_t addr) {
    asm volatile("ldmatrix.sync.aligned.m8n8.x4.shared.b16 {%0,%1,%2,%3}, [%4];"
        : "=r"(r[0]), "=r"(r[1]), "=r"(r[2]), "=r"(r[3]) : "r"(addr));
}
__device__ __forceinline__ void ldsm_x2(uint32_t* r, uint32_t addr) {
    asm volatile("ldmatrix.sync.aligned.m8n8.x2.shared.b16 {%0,%1}, [%2];"
        : "=r"(r[0]), "=r"(r[1]) : "r"(addr));
}
__device__ __forceinline__ void mma16816(float* c, const uint32_t* a, const uint32_t* b) {
    asm volatile("mma.sync.aligned.m16n8k16.row.col.f32.bf16.bf16.f32 "
        "{%0,%1,%2,%3}, {%4,%5,%6,%7}, {%8,%9}, {%0,%1,%2,%3};"
        : "+f"(c[0]), "+f"(c[1]), "+f"(c[2]), "+f"(c[3])
        : "r"(a[0]), "r"(a[1]), "r"(a[2]), "r"(a[3]), "r"(b[0]), "r"(b[1]));
}
__device__ __forceinline__ void cp16(uint32_t s, const void* g) {
    asm volatile("cp.async.cg.shared.global [%0], [%1], 16;" :: "r"(s), "l"(g));
}
#define CP_COMMIT() asm volatile("cp.async.commit_group;" ::: "memory")
#define CP_WAIT(n)  asm volatile("cp.async.wait_group %0;" :: "n"(n) : "memory")
// pack two fp32 -> bf16x2 (upper = first operand), RN rounding == __float2bfloat16
__device__ __forceinline__ uint32_t cvt_bf16x2(float hi, float lo) {
    uint32_t r;
    asm("cvt.rn.bf16x2.f32 %0, %1, %2;" : "=r"(r) : "f"(hi), "f"(lo));
    return r;
}

// ------------------------- scratch (device globals) -------------------------
__device__ __align__(16) int   g_rowptr[NN + 1];
__device__ __align__(16) int   g_blksum[NBLK];
__device__ __align__(16) int   g_cursor[NN];
__device__ __align__(16) int   g_csr[ETOT];
__device__ __align__(16) float g_x0[NN * HIDD];
__device__ __align__(16) float g_agg[NN * 288];
__device__ __align__(16) float g_o1[NN * 288];
__device__ __align__(16) float g_h2[NN * HIDD];
__device__ __align__(16) float g_o2[NN * HIDD];
__device__ __align__(16) float g_h3[NN * HIDD];
__device__ __align__(16) float g_ls1[NN * 4];
__device__ __align__(16) float g_ld1[NN * 4];
__device__ __align__(16) float g_ls2[NN];
__device__ __align__(16) float g_ld2[NN];
__device__ __align__(16) float g_ls3[NN];
__device__ __align__(16) float g_ld3[NN];
__device__ __align__(16) float g_cvec[8 * 72];
// per-layer transposed hi/lo weights [N, Kp]
__device__ __align__(16) __nv_bfloat16 g_w0h[72 * 256],  g_w0l[72 * 256];
__device__ __align__(16) __nv_bfloat16 g_w1h[288 * 96],  g_w1l[288 * 96];
__device__ __align__(16) __nv_bfloat16 g_w2h[72 * 288],  g_w2l[72 * 288];
__device__ __align__(16) __nv_bfloat16 g_w3h[72 * 96],   g_w3l[72 * 96];

// ------------------------------ CSR build ----------------------------------
__global__ void k_count_deg(const int* __restrict__ ei) {
    int e = blockIdx.x * blockDim.x + threadIdx.x;
    if (e < EE) atomicAdd(&g_rowptr[ei[EE + e]], 1);
}
// per-block exclusive scan of (deg_e + 1); block total -> g_blksum
__global__ void __launch_bounds__(256) k_scan_blk() {
    __shared__ int wsum[8];
    int tid = threadIdx.x, lane = tid & 31, wid = tid >> 5;
    int idx = blockIdx.x * 256 + tid;
    int v = (idx < NN) ? g_rowptr[idx] + 1 : 0;   // +1 = self loop, folded
    int x = v;
    #pragma unroll
    for (int o = 1; o < 32; o <<= 1) {
        int y = __shfl_up_sync(0xffffffffu, x, o);
        if (lane >= o) x += y;
    }
    if (lane == 31) wsum[wid] = x;
    __syncthreads();
    if (wid == 0 && lane < 8) {
        int s = wsum[lane];
        #pragma unroll
        for (int o = 1; o < 8; o <<= 1) {
            int y = __shfl_up_sync(0x000000ffu, s, o);
            if (lane >= o) s += y;
        }
        wsum[lane] = s;
    }
    __syncthreads();
    int excl = (wid ? wsum[wid - 1] : 0) + x - v;
    if (idx < NN) g_rowptr[idx] = excl;
    if (tid == 0) g_blksum[blockIdx.x] = wsum[7];
}
__global__ void __launch_bounds__(256) k_scan_top() {
    __shared__ int wsum[8];
    int tid = threadIdx.x, lane = tid & 31, wid = tid >> 5;
    int v = (tid < NBLK) ? g_blksum[tid] : 0;
    int x = v;
    #pragma unroll
    for (int o = 1; o < 32; o <<= 1) {
        int y = __shfl_up_sync(0xffffffffu, x, o);
        if (lane >= o) x += y;
    }
    if (lane == 31) wsum[wid] = x;
    __syncthreads();
    if (wid == 0 && lane < 8) {
        int s = wsum[lane];
        #pragma unroll
        for (int o = 1; o < 8; o <<= 1) {
            int y = __shfl_up_sync(0x000000ffu, s, o);
            if (lane >= o) s += y;
        }
        wsum[lane] = s;
    }
    __syncthreads();
    int excl = (wid ? wsum[wid - 1] : 0) + x - v;
    if (tid < NBLK) g_blksum[tid] = excl;
}
__global__ void k_add_self() {
    int i = blockIdx.x * blockDim.x + threadIdx.x;
    if (i < NN) {
        int r = g_rowptr[i] + g_blksum[i >> 8];
        g_rowptr[i] = r;
        g_csr[r] = i;
        g_cursor[i] = r + 1;
    }
    if (i == 0) g_rowptr[NN] = ETOT;
}
__global__ void k_scatter(const int* __restrict__ ei) {
    int e = blockIdx.x * blockDim.x + threadIdx.x;
    if (e < EE) {
        int s = ei[e];
        int d = ei[EE + e];
        int pos = atomicAdd(&g_cursor[d], 1);
        g_csr[pos] = s;
    }
}

// --------------- one-shot prep: all weight hi/lo transposes + cvec -----------
__device__ __forceinline__ void cvt1(const float* W, __nv_bfloat16* H, __nv_bfloat16* L,
                                     int e, int K, int N, int Kp) {
    int n = e / Kp, k = e - n * Kp;
    float v = (k < K) ? W[(size_t)k * N + n] : 0.f;
    __nv_bfloat16 h = __float2bfloat16(v);
    H[e] = h;
    L[e] = __float2bfloat16(v - __bfloat162float(h));
}
__global__ void k_prep(const float* __restrict__ W_in, const float* __restrict__ W1,
                       const float* __restrict__ W2, const float* __restrict__ W3,
                       const float* __restrict__ as1, const float* __restrict__ ad1)
{
    int idx = blockIdx.x * blockDim.x + threadIdx.x;
    if (idx < 18432) {
        cvt1(W_in, g_w0h, g_w0l, idx, 256, 72, 256);
    } else if (idx < 46080) {
        cvt1(W1, g_w1h, g_w1l, idx - 18432, 72, 288, 96);
    } else if (idx < 66816) {
        cvt1(W2, g_w2h, g_w2l, idx - 46080, 288, 72, 288);
    } else if (idx < 73728) {
        cvt1(W3, g_w3h, g_w3l, idx - 66816, 72, 72, 96);
    } else if (idx < 74304) {
        int t = idx - 73728;
        int which = t / 288;
        int r = t % 288;
        int h = r / 72, k = r % 72;
        const float* a = (which ? ad1 : as1) + h * 72;
        const float* wrow = W1 + (size_t)k * 288 + h * 72;
        float s = 0.f;
        #pragma unroll 8
        for (int c = 0; c < 72; c++) s += wrow[c] * a[c];
        g_cvec[t] = s;
    }
}

// ---- layer-1 logits straight from x0 (cvec identity) ------------------------
__global__ void __launch_bounds__(256) k_logits8(
    const float* __restrict__ x0, float* __restrict__ ls, float* __restrict__ ld)
{
    __shared__ float cs[288], cd[288];
    for (int i = threadIdx.x; i < 288; i += 256) {
        cs[i] = g_cvec[i];
        cd[i] = g_cvec[288 + i];
    }
    __syncthreads();
    int n = blockIdx.x * blockDim.x + threadIdx.x;
    if (n >= NN) return;
    const float* row = x0 + (size_t)n * 72;
    float s[4] = {0.f, 0.f, 0.f, 0.f}, d[4] = {0.f, 0.f, 0.f, 0.f};
    for (int k = 0; k < 72; k += 4) {
        float4 v = *(const float4*)(row + k);
        #pragma unroll
        for (int h = 0; h < 4; h++) {
            float4 a = *(const float4*)(cs + h * 72 + k);
            float4 b = *(const float4*)(cd + h * 72 + k);
            s[h] += v.x * a.x + v.y * a.y + v.z * a.z + v.w * a.w;
            d[h] += v.x * b.x + v.y * b.y + v.z * b.z + v.w * b.w;
        }
    }
    *(float4*)(ls + (size_t)n * 4) = make_float4(s[0], s[1], s[2], s[3]);
    *(float4*)(ld + (size_t)n * 4) = make_float4(d[0], d[1], d[2], d[3]);
}

// -------------------- pipelined mma.sync GEMM (round-14 form) ----------------
#define PITCH 40
#define BPART (72 * PITCH * 2)

__global__ void __launch_bounds__(384, 2)
k_mmagemm(const float* __restrict__ A, int aStride, int aColShift,
          const __nv_bfloat16* __restrict__ Bh, const __nv_bfloat16* __restrict__ Bl,
          const float* __restrict__ bias, float* __restrict__ C,
          const float* __restrict__ asrc, const float* __restrict__ adst,
          float* __restrict__ ls, float* __restrict__ ld, int lstride,
          int M, int Kin, int KoutTot, int useBias, int actELU)
{
    __shared__ __nv_bfloat16 sAh[128 * PITCH];
    __shared__ __nv_bfloat16 sAl[128 * PITCH];
    __shared__ __nv_bfloat16 sB[2][2][72 * PITCH];
    __shared__ float sLs[128];
    __shared__ float sLd[128];

    int tid = threadIdx.x, wid = tid >> 5, lane = tid & 31;
    int warpM = wid & 3;
    int warpN = wid >> 2;
    int r0 = blockIdx.x * 128;
    int c0 = blockIdx.y * 72;
    int Kp = (Kin + 31) & ~31;
    int aBase = aColShift ? c0 : 0;
    const int chunks = Kp >> 5;

    float acc[2][3][4];
    #pragma unroll
    for (int mi = 0; mi < 2; mi++)
        #pragma unroll
        for (int ni = 0; ni < 3; ni++)
            #pragma unroll
            for (int q = 0; q < 4; q++) acc[mi][ni][q] = 0.f;

    uint32_t uAh = smem_to_u32(sAh), uAl = smem_to_u32(sAl);
    uint32_t uB  = smem_to_u32(sB);

    int lm = lane >> 3, lj = lane & 7;
    uint32_t aoffA = (uint32_t)(warpM * 32 + (lm & 1) * 8 + lj) * (PITCH * 2) + (lm >> 1) * 16;
    uint32_t aoffB = (uint32_t)(warpN * 24 + lj) * (PITCH * 2) + (lm & 1) * 16;

    auto loadA4 = [&](int idx, int kbase) -> float4 {
        int row = idx >> 3, seg = idx & 7;
        int gr = r0 + row;
        int gc = kbase + seg * 4;
        float4 v = make_float4(0.f, 0.f, 0.f, 0.f);
        if (gr < M) {
            const float* ap = A + (size_t)gr * aStride + aBase;
            if (gc + 3 < Kin) v = *(const float4*)(ap + gc);
            else {
                if (gc + 0 < Kin) v.x = ap[gc + 0];
                if (gc + 1 < Kin) v.y = ap[gc + 1];
                if (gc + 2 < Kin) v.z = ap[gc + 2];
                if (gc + 3 < Kin) v.w = ap[gc + 3];
            }
        }
        return v;
    };
    // packed bf16x2 hi/lo split: same RN rounding, half the convert/STS issue
    auto storeA4 = [&](int idx, float4 v) {
        int row = idx >> 3, seg = idx & 7;
        uint32_t h01 = cvt_bf16x2(v.y, v.x);
        uint32_t h23 = cvt_bf16x2(v.w, v.z);
        float hx = __uint_as_float(h01 << 16);
        float hy = __uint_as_float(h01 & 0xffff0000u);
        float hz = __uint_as_float(h23 << 16);
        float hw = __uint_as_float(h23 & 0xffff0000u);
        uint32_t l01 = cvt_bf16x2(v.y - hy, v.x - hx);
        uint32_t l23 = cvt_bf16x2(v.w - hw, v.z - hz);
        *(uint2*)(sAh + row * PITCH + seg * 4) = make_uint2(h01, h23);
        *(uint2*)(sAl + row * PITCH + seg * 4) = make_uint2(l01, l23);
    };
    auto stageB = [&](int ch) {
        int kbase = ch << 5;
        int buf = ch & 1;
        #pragma unroll
        for (int rep = 0; rep < 2; rep++) {
            int idx = tid + rep * 384;
            if (idx < 576) {
                int part = (idx >= 288);
                int e = part ? idx - 288 : idx;
                int r = e >> 2, seg = e & 3;
                const __nv_bfloat16* gp =
                    (part ? Bl : Bh) + (size_t)(c0 + r) * Kp + kbase + seg * 8;
                uint32_t sp = uB + (uint32_t)(buf * 2 + part) * BPART
                                 + (uint32_t)r * (PITCH * 2) + seg * 16;
                cp16(sp, gp);
            }
        }
    };

    // ---- prologue ----
    stageB(0);
    CP_COMMIT();
    float4 aReg0 = loadA4(tid, 0);
    float4 aReg1 = loadA4(tid + 384, 0);
    float4 aReg2 = (tid < 256) ? loadA4(tid + 768, 0) : make_float4(0.f, 0.f, 0.f, 0.f);

    for (int ch = 0; ch < chunks; ch++) {
        storeA4(tid, aReg0);
        storeA4(tid + 384, aReg1);
        if (tid < 256) storeA4(tid + 768, aReg2);

        bool more = (ch + 1 < chunks);
        if (more) {
            int kb = (ch + 1) << 5;
            aReg0 = loadA4(tid, kb);
            aReg1 = loadA4(tid + 384, kb);
            if (tid < 256) aReg2 = loadA4(tid + 768, kb);
            stageB(ch + 1);
            CP_COMMIT();
            CP_WAIT(1);
        } else {
            CP_WAIT(0);
        }
        __syncthreads();

        uint32_t bufOff = (uint32_t)(ch & 1) * 2 * BPART;
        int kRem = Kin - (ch << 5);   // valid columns in this chunk
        #pragma unroll
        for (int ks = 0; ks < 2; ks++) {
            if (ks * 16 >= kRem) break;    // skip all-zero padded k16 step (exact)
            uint32_t kb = ks * 32;
            uint32_t fah[2][4], fal[2][4], fbh[3][2], fbl[3][2];
            #pragma unroll
            for (int mi = 0; mi < 2; mi++) {
                uint32_t off = aoffA + (uint32_t)mi * 16 * (PITCH * 2) + kb;
                ldsm_x4(fah[mi], uAh + off);
                ldsm_x4(fal[mi], uAl + off);
            }
            #pragma unroll
            for (int ni = 0; ni < 3; ni++) {
                uint32_t off = aoffB + (uint32_t)ni * 8 * (PITCH * 2) + kb;
                ldsm_x2(fbh[ni], uB + bufOff + off);
                ldsm_x2(fbl[ni], uB + bufOff + BPART + off);
            }
            #pragma unroll
            for (int mi = 0; mi < 2; mi++)
                #pragma unroll
                for (int ni = 0; ni < 3; ni++) {
                    mma16816(acc[mi][ni], fah[mi], fbh[ni]);
                    mma16816(acc[mi][ni], fal[mi], fbh[ni]);
                    mma16816(acc[mi][ni], fah[mi], fbl[ni]);
                }
        }
        __syncthreads();
    }

    // ---- store C (+bias, +ELU) ----
    int rb = r0 + warpM * 32 + (lane >> 2);
    int cb = c0 + warpN * 24 + (lane & 3) * 2;
    #pragma unroll
    for (int mi = 0; mi < 2; mi++) {
        #pragma unroll
        for (int ni = 0; ni < 3; ni++) {
            int r = rb + mi * 16;
            int c = cb + ni * 8;
            float2 v0 = make_float2(acc[mi][ni][0], acc[mi][ni][1]);
            float2 v1 = make_float2(acc[mi][ni][2], acc[mi][ni][3]);
            if (useBias) {
                float bx = __ldg(bias + c), by = __ldg(bias + c + 1);
                v0.x += bx; v0.y += by;
                v1.x += bx; v1.y += by;
            }
            if (actELU) {
                v0.x = (v0.x > 0.f) ? v0.x : expm1f(v0.x);
                v0.y = (v0.y > 0.f) ? v0.y : expm1f(v0.y);
                v1.x = (v1.x > 0.f) ? v1.x : expm1f(v1.x);
                v1.y = (v1.y > 0.f) ? v1.y : expm1f(v1.y);
            }
            if (r < M)     *(float2*)(C + (size_t)r * KoutTot + c) = v0;
            if (r + 8 < M) *(float2*)(C + (size_t)(r + 8) * KoutTot + c) = v1;
        }
    }

    // ---- fused attention logits (single head; layers 2/3) ----
    if (ls != nullptr) {
        const float* av = asrc + blockIdx.y * 72;
        const float* dv = adst + blockIdx.y * 72;
        float as6[6], ad6[6];
        #pragma unroll
        for (int t6 = 0; t6 < 6; t6++) {
            int ni = t6 >> 1, j = t6 & 1;
            int cc = warpN * 24 + ni * 8 + (lane & 3) * 2 + j;
            as6[t6] = __ldg(av + cc);
            ad6[t6] = __ldg(dv + cc);
        }
        float sp[4], dp[4];
        #pragma unroll
        for (int mi = 0; mi < 2; mi++)
            #pragma unroll
            for (int half = 0; half < 2; half++) {
                float s = 0.f, d = 0.f;
                #pragma unroll
                for (int ni = 0; ni < 3; ni++) {
                    s += acc[mi][ni][half * 2 + 0] * as6[ni * 2 + 0];
                    s += acc[mi][ni][half * 2 + 1] * as6[ni * 2 + 1];
                    d += acc[mi][ni][half * 2 + 0] * ad6[ni * 2 + 0];
                    d += acc[mi][ni][half * 2 + 1] * ad6[ni * 2 + 1];
                }
                sp[mi * 2 + half] = s;
                dp[mi * 2 + half] = d;
            }
        #pragma unroll
        for (int k = 0; k < 4; k++) {
            #pragma unroll
            for (int o = 1; o < 4; o <<= 1) {
                sp[k] += __shfl_xor_sync(0xffffffffu, sp[k], o);
                dp[k] += __shfl_xor_sync(0xffffffffu, dp[k], o);
            }
        }
        if (tid < 128) { sLs[tid] = 0.f; sLd[tid] = 0.f; }
        __syncthreads();
        if ((lane & 3) == 0) {
            int rloc = warpM * 32 + (lane >> 2);
            atomicAdd(&sLs[rloc],      sp[0]); atomicAdd(&sLd[rloc],      dp[0]);
            atomicAdd(&sLs[rloc + 8],  sp[1]); atomicAdd(&sLd[rloc + 8],  dp[1]);
            atomicAdd(&sLs[rloc + 16], sp[2]); atomicAdd(&sLd[rloc + 16], dp[2]);
            atomicAdd(&sLs[rloc + 24], sp[3]); atomicAdd(&sLd[rloc + 24], dp[3]);
        }
        __syncthreads();
        if (tid < 128) {
            int gr = r0 + tid;
            if (gr < M) {
                ls[(size_t)gr * lstride + blockIdx.y] = sLs[tid];
                ld[(size_t)gr * lstride + blockIdx.y] = sLd[tid];
            }
        }
    }
}

// ------- layer-1 edge pass: aggregate x0 (72 cols) under 4 head alphas -------
__global__ void __launch_bounds__(256) k_edge4agg(
    const float* __restrict__ x0, const float* __restrict__ ls,
    const float* __restrict__ ld, float* __restrict__ agg)
{
    int node = (blockIdx.x * blockDim.x + threadIdx.x) >> 5;
    if (node >= NN) return;
    int lane = threadIdx.x & 31;
    int s0 = g_rowptr[node], s1 = g_rowptr[node + 1];

    float4 ldv = __ldg((const float4*)ld + node);
    bool act = (lane < 18);

    float4 a0 = make_float4(0.f, 0.f, 0.f, 0.f);
    float4 a1 = a0, a2 = a0, a3 = a0;
    float  sum0 = 0.f, sum1 = 0.f, sum2 = 0.f, sum3 = 0.f;

    #pragma unroll 4
    for (int i = s0; i < s1; i++) {
        int s = g_csr[i];
        float4 lv = __ldg((const float4*)ls + s);
        float v0 = lv.x + ldv.x; v0 = fmaxf(v0, 0.2f * v0);
        float v1 = lv.y + ldv.y; v1 = fmaxf(v1, 0.2f * v1);
        float v2 = lv.z + ldv.z; v2 = fmaxf(v2, 0.2f * v2);
        float v3 = lv.w + ldv.w; v3 = fmaxf(v3, 0.2f * v3);
        float p0 = __expf(v0), p1 = __expf(v1);
        float p2 = __expf(v2), p3 = __expf(v3);
        sum0 += p0; sum1 += p1; sum2 += p2; sum3 += p3;

        if (act) {
            float4 v = __ldg((const float4*)(x0 + (size_t)s * 72) + lane);
            a0.x += p0 * v.x; a0.y += p0 * v.y; a0.z += p0 * v.z; a0.w += p0 * v.w;
            a1.x += p1 * v.x; a1.y += p1 * v.y; a1.z += p1 * v.z; a1.w += p1 * v.w;
            a2.x += p2 * v.x; a2.y += p2 * v.y; a2.z += p2 * v.z; a2.w += p2 * v.w;
            a3.x += p3 * v.x; a3.y += p3 * v.y; a3.z += p3 * v.z; a3.w += p3 * v.w;
        }
    }

    if (act) {
        float i0 = 1.f / fmaxf(sum0, 1e-16f);
        float i1 = 1.f / fmaxf(sum1, 1e-16f);
        float i2 = 1.f / fmaxf(sum2, 1e-16f);
        float i3 = 1.f / fmaxf(sum3, 1e-16f);
        float* o = agg + (size_t)node * 288 + lane * 4;
        *(float4*)(o)       = make_float4(a0.x * i0, a0.y * i0, a0.z * i0, a0.w * i0);
        *(float4*)(o + 72)  = make_float4(a1.x * i1, a1.y * i1, a1.z * i1, a1.w * i1);
        *(float4*)(o + 144) = make_float4(a2.x * i2, a2.y * i2, a2.z * i2, a2.w * i2);
        *(float4*)(o + 216) = make_float4(a3.x * i3, a3.y * i3, a3.z * i3, a3.w * i3);
    }
}

// --------------- single-head edge pass (layer 2), float4 gather ---------------
__global__ void __launch_bounds__(256) k_edge1(
    const float* __restrict__ hfeat, const float* __restrict__ ls,
    const float* __restrict__ ld, const float* __restrict__ bias,
    float* __restrict__ outp)
{
    int node = (blockIdx.x * blockDim.x + threadIdx.x) >> 5;
    if (node >= NN) return;
    int lane = threadIdx.x & 31;
    int s0 = g_rowptr[node], s1 = g_rowptr[node + 1];

    float ldv = __ldg(ld + node);
    bool act = (lane < 18);
    float4 acc = make_float4(0.f, 0.f, 0.f, 0.f);
    float  sum = 0.f;

    #pragma unroll 4
    for (int i = s0; i < s1; i++) {
        int s = g_csr[i];
        float v = __ldg(ls + s) + ldv;
        v = fmaxf(v, 0.2f * v);
        float p = __expf(v);
        sum += p;
        if (act) {
            float4 h = __ldg((const float4*)(hfeat + (size_t)s * 72) + lane);
            acc.x += p * h.x; acc.y += p * h.y;
            acc.z += p * h.z; acc.w += p * h.w;
        }
    }

    if (act) {
        float inv = 1.f / fmaxf(sum, 1e-16f);
        int c = lane * 4;
        float4 b = __ldg((const float4*)(bias + c));
        float4 r;
        r.x = acc.x * inv + b.x; r.x = (r.x > 0.f) ? r.x : expm1f(r.x);
        r.y = acc.y * inv + b.y; r.y = (r.y > 0.f) ? r.y : expm1f(r.y);
        r.z = acc.z * inv + b.z; r.z = (r.z > 0.f) ? r.z : expm1f(r.z);
        r.w = acc.w * inv + b.w; r.w = (r.w > 0.f) ? r.w : expm1f(r.w);
        *(float4*)(outp + (size_t)node * 72 + c) = r;
    }
}

// ---- layer-3 edge pass fused with residual + score MLP (final output) -------
__global__ void __launch_bounds__(256) k_edge1f(
    const float* __restrict__ hfeat, const float* __restrict__ ls,
    const float* __restrict__ ld, const float* __restrict__ bias,
    const float* __restrict__ x0,
    const float* __restrict__ Ws1, const float* __restrict__ bs1,
    const float* __restrict__ Ws2, const float* __restrict__ bs2,
    float* __restrict__ out)
{
    __shared__ float w1s[72 * 32];
    __shared__ float w2s[32];
    __shared__ float b1s[32];
    __shared__ float b2s;
    __shared__ __align__(16) float vbuf[8][72];

    for (int i = threadIdx.x; i < 72 * 32; i += 256) w1s[i] = Ws1[i];
    if (threadIdx.x < 32) {
        w2s[threadIdx.x] = Ws2[threadIdx.x];
        b1s[threadIdx.x] = bs1[threadIdx.x];
    }
    if (threadIdx.x == 0) b2s = bs2[0];
    __syncthreads();

    int node = (blockIdx.x * blockDim.x + threadIdx.x) >> 5;
    if (node >= NN) return;
    int lane = threadIdx.x & 31;
    int warp = threadIdx.x >> 5;
    int s0 = g_rowptr[node], s1 = g_rowptr[node + 1];

    float ldv = __ldg(ld + node);
    bool act = (lane < 18);
    float4 acc = make_float4(0.f, 0.f, 0.f, 0.f);
    float  sum = 0.f;

    #pragma unroll 4
    for (int i = s0; i < s1; i++) {
        int s = g_csr[i];
        float v = __ldg(ls + s) + ldv;
        v = fmaxf(v, 0.2f * v);
        float p = __expf(v);
        sum += p;
        if (act) {
            float4 h = __ldg((const float4*)(hfeat + (size_t)s * 72) + lane);
            acc.x += p * h.x; acc.y += p * h.y;
            acc.z += p * h.z; acc.w += p * h.w;
        }
    }

    if (act) {
        float inv = 1.f / fmaxf(sum, 1e-16f);
        int c = lane * 4;
        float4 b = __ldg((const float4*)(bias + c));
        float4 xv = __ldg((const float4*)(x0 + (size_t)node * 72) + lane);
        float4 r;
        r.x = acc.x * inv + b.x; r.x = ((r.x > 0.f) ? r.x : expm1f(r.x)) + xv.x;
        r.y = acc.y * inv + b.y; r.y = ((r.y > 0.f) ? r.y : expm1f(r.y)) + xv.y;
        r.z = acc.z * inv + b.z; r.z = ((r.z > 0.f) ? r.z : expm1f(r.z)) + xv.z;
        r.w = acc.w * inv + b.w; r.w = ((r.w > 0.f) ? r.w : expm1f(r.w)) + xv.w;
        *(float4*)(&vbuf[warp][c]) = r;
    }
    __syncwarp();

    // score MLP: lane j owns hidden unit j
    float t = b1s[lane];
    #pragma unroll 8
    for (int k = 0; k < 72; k++) t += vbuf[warp][k] * w1s[k * 32 + lane];
    float sc = fmaxf(t, 0.f) * w2s[lane];
    #pragma unroll
    for (int o = 16; o > 0; o >>= 1) sc += __shfl_xor_sync(0xffffffffu, sc, o);
    if (lane == 0) out[node] = sc + b2s;
}

// ------------------------------ launch ---------------------------------------
extern "C" void kernel_launch(void* const* d_in, const int* in_sizes, int n_in,
                              void* d_out, int out_size)
{
    const float* x    = (const float*)d_in[0];
    const int*   ei   = (const int*)d_in[1];
    const float* W_in = (const float*)d_in[2];
    const float* b_in = (const float*)d_in[3];
    const float* W1   = (const float*)d_in[4];
    const float* as1  = (const float*)d_in[5];
    const float* ad1  = (const float*)d_in[6];
    const float* b1   = (const float*)d_in[7];
    const float* W2   = (const float*)d_in[8];
    const float* as2  = (const float*)d_in[9];
    const float* ad2  = (const float*)d_in[10];
    const float* b2   = (const float*)d_in[11];
    const float* W3   = (const float*)d_in[12];
    const float* as3  = (const float*)d_in[13];
    const float* ad3  = (const float*)d_in[14];
    const float* b3   = (const float*)d_in[15];
    const float* Ws1  = (const float*)d_in[16];
    const float* bs1  = (const float*)d_in[17];
    const float* Ws2  = (const float*)d_in[18];
    const float* bs2  = (const float*)d_in[19];
    float* out = (float*)d_out;

    float *px0, *pagg, *po1, *ph2, *po2, *ph3;
    float *pls1, *pld1, *pls2, *pld2, *pls3, *pld3;
    int* prowptr;
    __nv_bfloat16 *pw0h, *pw0l, *pw1h, *pw1l, *pw2h, *pw2l, *pw3h, *pw3l;
    cudaGetSymbolAddress((void**)&px0,  g_x0);
    cudaGetSymbolAddress((void**)&pagg, g_agg);
    cudaGetSymbolAddress((void**)&po1,  g_o1);
    cudaGetSymbolAddress((void**)&ph2,  g_h2);
    cudaGetSymbolAddress((void**)&po2,  g_o2);
    cudaGetSymbolAddress((void**)&ph3,  g_h3);
    cudaGetSymbolAddress((void**)&pls1, g_ls1);
    cudaGetSymbolAddress((void**)&pld1, g_ld1);
    cudaGetSymbolAddress((void**)&pls2, g_ls2);
    cudaGetSymbolAddress((void**)&pld2, g_ld2);
    cudaGetSymbolAddress((void**)&pls3, g_ls3);
    cudaGetSymbolAddress((void**)&pld3, g_ld3);
    cudaGetSymbolAddress((void**)&prowptr, g_rowptr);
    cudaGetSymbolAddress((void**)&pw0h, g_w0h);
    cudaGetSymbolAddress((void**)&pw0l, g_w0l);
    cudaGetSymbolAddress((void**)&pw1h, g_w1h);
    cudaGetSymbolAddress((void**)&pw1l, g_w1l);
    cudaGetSymbolAddress((void**)&pw2h, g_w2h);
    cudaGetSymbolAddress((void**)&pw2l, g_w2l);
    cudaGetSymbolAddress((void**)&pw3h, g_w3h);
    cudaGetSymbolAddress((void**)&pw3l, g_w3l);

    // side stream + fork/join events (capture-safe: branches recorded into graph)
    cudaStream_t side;
    cudaStreamCreateWithFlags(&side, cudaStreamNonBlocking);
    cudaEvent_t eFork, eJoin;
    cudaEventCreateWithFlags(&eFork, cudaEventDisableTiming);
    cudaEventCreateWithFlags(&eJoin, cudaEventDisableTiming);

    // fork: CSR build runs concurrently with layer-0 compute
    cudaEventRecord(eFork, 0);
    cudaStreamWaitEvent(side, eFork, 0);

    // --- side branch: CSR build ---
    cudaMemsetAsync(prowptr, 0, (NN + 1) * sizeof(int), side);
    k_count_deg<<<(EE + 255) / 256, 256, 0, side>>>(ei);
    k_scan_blk<<<NBLK, 256, 0, side>>>();
    k_scan_top<<<1, 256, 0, side>>>();
    k_add_self<<<(NN + 255) / 256, 256, 0, side>>>();
    k_scatter<<<(EE + 255) / 256, 256, 0, side>>>(ei);
    cudaEventRecord(eJoin, side);

    // --- main branch: prep + layer-0 GEMM + layer-1 logits ---
    k_prep<<<(74304 + 255) / 256, 256>>>(W_in, W1, W2, W3, as1, ad1);
    k_mmagemm<<<dim3(391, 1), 384>>>(x, 256, 0, pw0h, pw0l, b_in, px0,
                                     nullptr, nullptr, nullptr, nullptr, 1,
                                     NN, 256, 72, 1, 0);
    k_logits8<<<(NN + 255) / 256, 256>>>(px0, pls1, pld1);

    // join: edge aggregation needs both CSR and logits
    cudaStreamWaitEvent(0, eJoin, 0);

    // --- layer 1 ---
    k_edge4agg<<<(NN * 32) / 256, 256>>>(px0, pls1, pld1, pagg);
    k_mmagemm<<<dim3(391, 4), 384>>>(pagg, 288, 1, pw1h, pw1l, b1, po1,
                                     nullptr, nullptr, nullptr, nullptr, 1,
                                     NN, 72, 288, 1, 1);

    // --- layer 2 ---
    k_mmagemm<<<dim3(391, 1), 384>>>(po1, 288, 0, pw2h, pw2l, nullptr, ph2,
                                     as2, ad2, pls2, pld2, 1,
                                     NN, 288, 72, 0, 0);
    k_edge1<<<(NN * 32) / 256, 256>>>(ph2, pls2, pld2, b2, po2);

    // --- layer 3 ---
    k_mmagemm<<<dim3(391, 1), 384>>>(po2, 72, 0, pw3h, pw3l, nullptr, ph3,
                                     as3, ad3, pls3, pld3, 1,
                                     NN, 72, 72, 0, 0);
    k_edge1f<<<(NN * 32) / 256, 256>>>(ph3, pls3, pld3, b3, px0,
                                       Ws1, bs1, Ws2, bs2, out);
}

// round 17
// speedup vs baseline: 1.0772x; 1.0120x over previous
#include <cuda_runtime.h>
#include <cuda_bf16.h>
#include <math.h>
#include <stdint.h>

#define NN   50000
#define EE   800000
#define ETOT (NN + EE)
#define IND  256
#define HIDD 72
#define NBLK ((NN + 255) / 256)   // 196

// ======================= warp-MMA helpers (baseline PTX) ====================
__device__ __forceinline__ uint32_t smem_to_u32(const void* p) {
    uint32_t a;
    asm("{ .reg .u64 t; cvta.to.shared.u64 t, %1; cvt.u32.u64 %0, t; }" : "=r"(a) : "l"(p));
    return a;
}
__device__ __forceinline__ void ldsm_x4(uint32_t* r, uint32_t addr) {
    asm volatile("ldmatrix.sync.aligned.m8n8.x4.shared.b16 {%0,%1,%2,%3}, [%4];"
        : "=r"(r[0]), "=r"(r[1]), "=r"(r[2]), "=r"(r[3]) : "r"(addr));
}
__device__ __forceinline__ void ldsm_x2(uint32_t* r, uint32_t addr) {
    asm volatile("ldmatrix.sync.aligned.m8n8.x2.shared.b16 {%0,%1}, [%2];"
        : "=r"(r[0]), "=r"(r[1]) : "r"(addr));
}
__device__ __forceinline__ void mma16816(float* c, const uint32_t* a, const uint32_t* b) {
    asm volatile("mma.sync.aligned.m16n8k16.row.col.f32.bf16.bf16.f32 "
        "{%0,%1,%2,%3}, {%4,%5,%6,%7}, {%8,%9}, {%0,%1,%2,%3};"
        : "+f"(c[0]), "+f"(c[1]), "+f"(c[2]), "+f"(c[3])
        : "r"(a[0]), "r"(a[1]), "r"(a[2]), "r"(a[3]), "r"(b[0]), "r"(b[1]));
}
__device__ __forceinline__ void cp16(uint32_t s, const void* g) {
    asm volatile("cp.async.cg.shared.global [%0], [%1], 16;" :: "r"(s), "l"(g));
}
#define CP_COMMIT() asm volatile("cp.async.commit_group;" ::: "memory")
#define CP_WAIT(n)  asm volatile("cp.async.wait_group %0;" :: "n"(n) : "memory")
// pack two fp32 -> bf16x2 (upper = first operand), RN rounding == __float2bfloat16
__device__ __forceinline__ uint32_t cvt_bf16x2(float hi, float lo) {
    uint32_t r;
    asm("cvt.rn.bf16x2.f32 %0, %1, %2;" : "=r"(r) : "f"(hi), "f"(lo));
    return r;
}

// ------------------------- scratch (device globals) -------------------------
__device__ __align__(16) int   g_rowptr[NN + 1];
__device__ __align__(16) int   g_blksum[NBLK];
__device__ __align__(16) int   g_cursor[NN];
__device__ __align__(16) int   g_csr[ETOT];
__device__ __align__(16) float g_x0[NN * HIDD];
__device__ __align__(16) float g_agg[NN * 288];
__device__ __align__(16) float g_o1[NN * 288];
__device__ __align__(16) float g_h2[NN * HIDD];
__device__ __align__(16) float g_o2[NN * HIDD];
__device__ __align__(16) float g_h3[NN * HIDD];
__device__ __align__(16) float g_ls1[NN * 4];
__device__ __align__(16) float g_ld1[NN * 4];
__device__ __align__(16) float g_ls2[NN];
__device__ __align__(16) float g_ld2[NN];
__device__ __align__(16) float g_ls3[NN];
__device__ __align__(16) float g_ld3[NN];
__device__ __align__(16) float g_cvec[8 * 72];
// per-layer transposed hi/lo weights [N, Kp]
__device__ __align__(16) __nv_bfloat16 g_w0h[72 * 256],  g_w0l[72 * 256];
__device__ __align__(16) __nv_bfloat16 g_w1h[288 * 96],  g_w1l[288 * 96];
__device__ __align__(16) __nv_bfloat16 g_w2h[72 * 288],  g_w2l[72 * 288];
__device__ __align__(16) __nv_bfloat16 g_w3h[72 * 96],   g_w3l[72 * 96];

// ------------------------------ CSR build ----------------------------------
__global__ void k_count_deg(const int* __restrict__ ei) {
    int e = blockIdx.x * blockDim.x + threadIdx.x;
    if (e < EE) atomicAdd(&g_rowptr[ei[EE + e]], 1);
}
// per-block exclusive scan of (deg_e + 1); block total -> g_blksum
__global__ void __launch_bounds__(256) k_scan_blk() {
    __shared__ int wsum[8];
    int tid = threadIdx.x, lane = tid & 31, wid = tid >> 5;
    int idx = blockIdx.x * 256 + tid;
    int v = (idx < NN) ? g_rowptr[idx] + 1 : 0;   // +1 = self loop, folded
    int x = v;
    #pragma unroll
    for (int o = 1; o < 32; o <<= 1) {
        int y = __shfl_up_sync(0xffffffffu, x, o);
        if (lane >= o) x += y;
    }
    if (lane == 31) wsum[wid] = x;
    __syncthreads();
    if (wid == 0 && lane < 8) {
        int s = wsum[lane];
        #pragma unroll
        for (int o = 1; o < 8; o <<= 1) {
            int y = __shfl_up_sync(0x000000ffu, s, o);
            if (lane >= o) s += y;
        }
        wsum[lane] = s;
    }
    __syncthreads();
    int excl = (wid ? wsum[wid - 1] : 0) + x - v;
    if (idx < NN) g_rowptr[idx] = excl;
    if (tid == 0) g_blksum[blockIdx.x] = wsum[7];
}
__global__ void __launch_bounds__(256) k_scan_top() {
    __shared__ int wsum[8];
    int tid = threadIdx.x, lane = tid & 31, wid = tid >> 5;
    int v = (tid < NBLK) ? g_blksum[tid] : 0;
    int x = v;
    #pragma unroll
    for (int o = 1; o < 32; o <<= 1) {
        int y = __shfl_up_sync(0xffffffffu, x, o);
        if (lane >= o) x += y;
    }
    if (lane == 31) wsum[wid] = x;
    __syncthreads();
    if (wid == 0 && lane < 8) {
        int s = wsum[lane];
        #pragma unroll
        for (int o = 1; o < 8; o <<= 1) {
            int y = __shfl_up_sync(0x000000ffu, s, o);
            if (lane >= o) s += y;
        }
        wsum[lane] = s;
    }
    __syncthreads();
    int excl = (wid ? wsum[wid - 1] : 0) + x - v;
    if (tid < NBLK) g_blksum[tid] = excl;
}
__global__ void k_add_self() {
    int i = blockIdx.x * blockDim.x + threadIdx.x;
    if (i < NN) {
        int r = g_rowptr[i] + g_blksum[i >> 8];
        g_rowptr[i] = r;
        g_csr[r] = i;
        g_cursor[i] = r + 1;
    }
    if (i == 0) g_rowptr[NN] = ETOT;
}
__global__ void k_scatter(const int* __restrict__ ei) {
    int e = blockIdx.x * blockDim.x + threadIdx.x;
    if (e < EE) {
        int s = ei[e];
        int d = ei[EE + e];
        int pos = atomicAdd(&g_cursor[d], 1);
        g_csr[pos] = s;
    }
}

// --------------- one-shot prep: all weight hi/lo transposes + cvec -----------
__device__ __forceinline__ void cvt1(const float* W, __nv_bfloat16* H, __nv_bfloat16* L,
                                     int e, int K, int N, int Kp) {
    int n = e / Kp, k = e - n * Kp;
    float v = (k < K) ? W[(size_t)k * N + n] : 0.f;
    __nv_bfloat16 h = __float2bfloat16(v);
    H[e] = h;
    L[e] = __float2bfloat16(v - __bfloat162float(h));
}
__global__ void k_prep(const float* __restrict__ W_in, const float* __restrict__ W1,
                       const float* __restrict__ W2, const float* __restrict__ W3,
                       const float* __restrict__ as1, const float* __restrict__ ad1)
{
    int idx = blockIdx.x * blockDim.x + threadIdx.x;
    if (idx < 18432) {
        cvt1(W_in, g_w0h, g_w0l, idx, 256, 72, 256);
    } else if (idx < 46080) {
        cvt1(W1, g_w1h, g_w1l, idx - 18432, 72, 288, 96);
    } else if (idx < 66816) {
        cvt1(W2, g_w2h, g_w2l, idx - 46080, 288, 72, 288);
    } else if (idx < 73728) {
        cvt1(W3, g_w3h, g_w3l, idx - 66816, 72, 72, 96);
    } else if (idx < 74304) {
        int t = idx - 73728;
        int which = t / 288;
        int r = t % 288;
        int h = r / 72, k = r % 72;
        const float* a = (which ? ad1 : as1) + h * 72;
        const float* wrow = W1 + (size_t)k * 288 + h * 72;
        float s = 0.f;
        #pragma unroll 8
        for (int c = 0; c < 72; c++) s += wrow[c] * a[c];
        g_cvec[t] = s;
    }
}

// ---- layer-1 logits straight from x0 (cvec identity) ------------------------
__global__ void __launch_bounds__(256) k_logits8(
    const float* __restrict__ x0, float* __restrict__ ls, float* __restrict__ ld)
{
    __shared__ float cs[288], cd[288];
    for (int i = threadIdx.x; i < 288; i += 256) {
        cs[i] = g_cvec[i];
        cd[i] = g_cvec[288 + i];
    }
    __syncthreads();
    int n = blockIdx.x * blockDim.x + threadIdx.x;
    if (n >= NN) return;
    const float* row = x0 + (size_t)n * 72;
    float s[4] = {0.f, 0.f, 0.f, 0.f}, d[4] = {0.f, 0.f, 0.f, 0.f};
    for (int k = 0; k < 72; k += 4) {
        float4 v = *(const float4*)(row + k);
        #pragma unroll
        for (int h = 0; h < 4; h++) {
            float4 a = *(const float4*)(cs + h * 72 + k);
            float4 b = *(const float4*)(cd + h * 72 + k);
            s[h] += v.x * a.x + v.y * a.y + v.z * a.z + v.w * a.w;
            d[h] += v.x * b.x + v.y * b.y + v.z * b.z + v.w * b.w;
        }
    }
    *(float4*)(ls + (size_t)n * 4) = make_float4(s[0], s[1], s[2], s[3]);
    *(float4*)(ld + (size_t)n * 4) = make_float4(d[0], d[1], d[2], d[3]);
}

// -------------------- pipelined mma.sync GEMM (round-16 form) ----------------
#define PITCH 40
#define BPART (72 * PITCH * 2)

__global__ void __launch_bounds__(384, 2)
k_mmagemm(const float* __restrict__ A, int aStride, int aColShift,
          const __nv_bfloat16* __restrict__ Bh, const __nv_bfloat16* __restrict__ Bl,
          const float* __restrict__ bias, float* __restrict__ C,
          const float* __restrict__ asrc, const float* __restrict__ adst,
          float* __restrict__ ls, float* __restrict__ ld, int lstride,
          int M, int Kin, int KoutTot, int useBias, int actELU)
{
    __shared__ __nv_bfloat16 sAh[128 * PITCH];
    __shared__ __nv_bfloat16 sAl[128 * PITCH];
    __shared__ __nv_bfloat16 sB[2][2][72 * PITCH];
    __shared__ float sLs[128];
    __shared__ float sLd[128];

    int tid = threadIdx.x, wid = tid >> 5, lane = tid & 31;
    int warpM = wid & 3;
    int warpN = wid >> 2;
    int r0 = blockIdx.x * 128;
    int c0 = blockIdx.y * 72;
    int Kp = (Kin + 31) & ~31;
    int aBase = aColShift ? c0 : 0;
    const int chunks = Kp >> 5;

    float acc[2][3][4];
    #pragma unroll
    for (int mi = 0; mi < 2; mi++)
        #pragma unroll
        for (int ni = 0; ni < 3; ni++)
            #pragma unroll
            for (int q = 0; q < 4; q++) acc[mi][ni][q] = 0.f;

    uint32_t uAh = smem_to_u32(sAh), uAl = smem_to_u32(sAl);
    uint32_t uB  = smem_to_u32(sB);

    int lm = lane >> 3, lj = lane & 7;
    uint32_t aoffA = (uint32_t)(warpM * 32 + (lm & 1) * 8 + lj) * (PITCH * 2) + (lm >> 1) * 16;
    uint32_t aoffB = (uint32_t)(warpN * 24 + lj) * (PITCH * 2) + (lm & 1) * 16;

    auto loadA4 = [&](int idx, int kbase) -> float4 {
        int row = idx >> 3, seg = idx & 7;
        int gr = r0 + row;
        int gc = kbase + seg * 4;
        float4 v = make_float4(0.f, 0.f, 0.f, 0.f);
        if (gr < M) {
            const float* ap = A + (size_t)gr * aStride + aBase;
            if (gc + 3 < Kin) v = *(const float4*)(ap + gc);
            else {
                if (gc + 0 < Kin) v.x = ap[gc + 0];
                if (gc + 1 < Kin) v.y = ap[gc + 1];
                if (gc + 2 < Kin) v.z = ap[gc + 2];
                if (gc + 3 < Kin) v.w = ap[gc + 3];
            }
        }
        return v;
    };
    // packed bf16x2 hi/lo split: same RN rounding, half the convert/STS issue
    auto storeA4 = [&](int idx, float4 v) {
        int row = idx >> 3, seg = idx & 7;
        uint32_t h01 = cvt_bf16x2(v.y, v.x);
        uint32_t h23 = cvt_bf16x2(v.w, v.z);
        float hx = __uint_as_float(h01 << 16);
        float hy = __uint_as_float(h01 & 0xffff0000u);
        float hz = __uint_as_float(h23 << 16);
        float hw = __uint_as_float(h23 & 0xffff0000u);
        uint32_t l01 = cvt_bf16x2(v.y - hy, v.x - hx);
        uint32_t l23 = cvt_bf16x2(v.w - hw, v.z - hz);
        *(uint2*)(sAh + row * PITCH + seg * 4) = make_uint2(h01, h23);
        *(uint2*)(sAl + row * PITCH + seg * 4) = make_uint2(l01, l23);
    };
    auto stageB = [&](int ch) {
        int kbase = ch << 5;
        int buf = ch & 1;
        #pragma unroll
        for (int rep = 0; rep < 2; rep++) {
            int idx = tid + rep * 384;
            if (idx < 576) {
                int part = (idx >= 288);
                int e = part ? idx - 288 : idx;
                int r = e >> 2, seg = e & 3;
                const __nv_bfloat16* gp =
                    (part ? Bl : Bh) + (size_t)(c0 + r) * Kp + kbase + seg * 8;
                uint32_t sp = uB + (uint32_t)(buf * 2 + part) * BPART
                                 + (uint32_t)r * (PITCH * 2) + seg * 16;
                cp16(sp, gp);
            }
        }
    };

    // ---- prologue ----
    stageB(0);
    CP_COMMIT();
    float4 aReg0 = loadA4(tid, 0);
    float4 aReg1 = loadA4(tid + 384, 0);
    float4 aReg2 = (tid < 256) ? loadA4(tid + 768, 0) : make_float4(0.f, 0.f, 0.f, 0.f);

    for (int ch = 0; ch < chunks; ch++) {
        storeA4(tid, aReg0);
        storeA4(tid + 384, aReg1);
        if (tid < 256) storeA4(tid + 768, aReg2);

        bool more = (ch + 1 < chunks);
        if (more) {
            int kb = (ch + 1) << 5;
            aReg0 = loadA4(tid, kb);
            aReg1 = loadA4(tid + 384, kb);
            if (tid < 256) aReg2 = loadA4(tid + 768, kb);
            stageB(ch + 1);
            CP_COMMIT();
            CP_WAIT(1);
        } else {
            CP_WAIT(0);
        }
        __syncthreads();

        uint32_t bufOff = (uint32_t)(ch & 1) * 2 * BPART;
        int kRem = Kin - (ch << 5);   // valid columns in this chunk
        #pragma unroll
        for (int ks = 0; ks < 2; ks++) {
            if (ks * 16 >= kRem) break;    // skip all-zero padded k16 step (exact)
            uint32_t kb = ks * 32;
            uint32_t fah[2][4], fal[2][4], fbh[3][2], fbl[3][2];
            #pragma unroll
            for (int mi = 0; mi < 2; mi++) {
                uint32_t off = aoffA + (uint32_t)mi * 16 * (PITCH * 2) + kb;
                ldsm_x4(fah[mi], uAh + off);
                ldsm_x4(fal[mi], uAl + off);
            }
            #pragma unroll
            for (int ni = 0; ni < 3; ni++) {
                uint32_t off = aoffB + (uint32_t)ni * 8 * (PITCH * 2) + kb;
                ldsm_x2(fbh[ni], uB + bufOff + off);
                ldsm_x2(fbl[ni], uB + bufOff + BPART + off);
            }
            #pragma unroll
            for (int mi = 0; mi < 2; mi++)
                #pragma unroll
                for (int ni = 0; ni < 3; ni++) {
                    mma16816(acc[mi][ni], fah[mi], fbh[ni]);
                    mma16816(acc[mi][ni], fal[mi], fbh[ni]);
                    mma16816(acc[mi][ni], fah[mi], fbl[ni]);
                }
        }
        __syncthreads();
    }

    // ---- store C (+bias, +ELU) ----
    int rb = r0 + warpM * 32 + (lane >> 2);
    int cb = c0 + warpN * 24 + (lane & 3) * 2;
    #pragma unroll
    for (int mi = 0; mi < 2; mi++) {
        #pragma unroll
        for (int ni = 0; ni < 3; ni++) {
            int r = rb + mi * 16;
            int c = cb + ni * 8;
            float2 v0 = make_float2(acc[mi][ni][0], acc[mi][ni][1]);
            float2 v1 = make_float2(acc[mi][ni][2], acc[mi][ni][3]);
            if (useBias) {
                float bx = __ldg(bias + c), by = __ldg(bias + c + 1);
                v0.x += bx; v0.y += by;
                v1.x += bx; v1.y += by;
            }
            if (actELU) {
                v0.x = (v0.x > 0.f) ? v0.x : expm1f(v0.x);
                v0.y = (v0.y > 0.f) ? v0.y : expm1f(v0.y);
                v1.x = (v1.x > 0.f) ? v1.x : expm1f(v1.x);
                v1.y = (v1.y > 0.f) ? v1.y : expm1f(v1.y);
            }
            if (r < M)     *(float2*)(C + (size_t)r * KoutTot + c) = v0;
            if (r + 8 < M) *(float2*)(C + (size_t)(r + 8) * KoutTot + c) = v1;
        }
    }

    // ---- fused attention logits (single head; layers 2/3) ----
    if (ls != nullptr) {
        const float* av = asrc + blockIdx.y * 72;
        const float* dv = adst + blockIdx.y * 72;
        float as6[6], ad6[6];
        #pragma unroll
        for (int t6 = 0; t6 < 6; t6++) {
            int ni = t6 >> 1, j = t6 & 1;
            int cc = warpN * 24 + ni * 8 + (lane & 3) * 2 + j;
            as6[t6] = __ldg(av + cc);
            ad6[t6] = __ldg(dv + cc);
        }
        float sp[4], dp[4];
        #pragma unroll
        for (int mi = 0; mi < 2; mi++)
            #pragma unroll
            for (int half = 0; half < 2; half++) {
                float s = 0.f, d = 0.f;
                #pragma unroll
                for (int ni = 0; ni < 3; ni++) {
                    s += acc[mi][ni][half * 2 + 0] * as6[ni * 2 + 0];
                    s += acc[mi][ni][half * 2 + 1] * as6[ni * 2 + 1];
                    d += acc[mi][ni][half * 2 + 0] * ad6[ni * 2 + 0];
                    d += acc[mi][ni][half * 2 + 1] * ad6[ni * 2 + 1];
                }
                sp[mi * 2 + half] = s;
                dp[mi * 2 + half] = d;
            }
        #pragma unroll
        for (int k = 0; k < 4; k++) {
            #pragma unroll
            for (int o = 1; o < 4; o <<= 1) {
                sp[k] += __shfl_xor_sync(0xffffffffu, sp[k], o);
                dp[k] += __shfl_xor_sync(0xffffffffu, dp[k], o);
            }
        }
        if (tid < 128) { sLs[tid] = 0.f; sLd[tid] = 0.f; }
        __syncthreads();
        if ((lane & 3) == 0) {
            int rloc = warpM * 32 + (lane >> 2);
            atomicAdd(&sLs[rloc],      sp[0]); atomicAdd(&sLd[rloc],      dp[0]);
            atomicAdd(&sLs[rloc + 8],  sp[1]); atomicAdd(&sLd[rloc + 8],  dp[1]);
            atomicAdd(&sLs[rloc + 16], sp[2]); atomicAdd(&sLd[rloc + 16], dp[2]);
            atomicAdd(&sLs[rloc + 24], sp[3]); atomicAdd(&sLd[rloc + 24], dp[3]);
        }
        __syncthreads();
        if (tid < 128) {
            int gr = r0 + tid;
            if (gr < M) {
                ls[(size_t)gr * lstride + blockIdx.y] = sLs[tid];
                ld[(size_t)gr * lstride + blockIdx.y] = sLd[tid];
            }
        }
    }
}

// ------- layer-1 edge pass: aggregate x0 (72 cols) under 4 head alphas -------
// 64-thread CTAs: max-of-2 warp skew instead of max-of-8 (degree imbalance)
__global__ void __launch_bounds__(64) k_edge4agg(
    const float* __restrict__ x0, const float* __restrict__ ls,
    const float* __restrict__ ld, float* __restrict__ agg)
{
    int node = (blockIdx.x * blockDim.x + threadIdx.x) >> 5;
    if (node >= NN) return;
    int lane = threadIdx.x & 31;
    int s0 = g_rowptr[node], s1 = g_rowptr[node + 1];

    float4 ldv = __ldg((const float4*)ld + node);
    bool act = (lane < 18);

    float4 a0 = make_float4(0.f, 0.f, 0.f, 0.f);
    float4 a1 = a0, a2 = a0, a3 = a0;
    float  sum0 = 0.f, sum1 = 0.f, sum2 = 0.f, sum3 = 0.f;

    #pragma unroll 4
    for (int i = s0; i < s1; i++) {
        int s = g_csr[i];
        float4 lv = __ldg((const float4*)ls + s);
        float v0 = lv.x + ldv.x; v0 = fmaxf(v0, 0.2f * v0);
        float v1 = lv.y + ldv.y; v1 = fmaxf(v1, 0.2f * v1);
        float v2 = lv.z + ldv.z; v2 = fmaxf(v2, 0.2f * v2);
        float v3 = lv.w + ldv.w; v3 = fmaxf(v3, 0.2f * v3);
        float p0 = __expf(v0), p1 = __expf(v1);
        float p2 = __expf(v2), p3 = __expf(v3);
        sum0 += p0; sum1 += p1; sum2 += p2; sum3 += p3;

        if (act) {
            float4 v = __ldg((const float4*)(x0 + (size_t)s * 72) + lane);
            a0.x += p0 * v.x; a0.y += p0 * v.y; a0.z += p0 * v.z; a0.w += p0 * v.w;
            a1.x += p1 * v.x; a1.y += p1 * v.y; a1.z += p1 * v.z; a1.w += p1 * v.w;
            a2.x += p2 * v.x; a2.y += p2 * v.y; a2.z += p2 * v.z; a2.w += p2 * v.w;
            a3.x += p3 * v.x; a3.y += p3 * v.y; a3.z += p3 * v.z; a3.w += p3 * v.w;
        }
    }

    if (act) {
        float i0 = 1.f / fmaxf(sum0, 1e-16f);
        float i1 = 1.f / fmaxf(sum1, 1e-16f);
        float i2 = 1.f / fmaxf(sum2, 1e-16f);
        float i3 = 1.f / fmaxf(sum3, 1e-16f);
        float* o = agg + (size_t)node * 288 + lane * 4;
        *(float4*)(o)       = make_float4(a0.x * i0, a0.y * i0, a0.z * i0, a0.w * i0);
        *(float4*)(o + 72)  = make_float4(a1.x * i1, a1.y * i1, a1.z * i1, a1.w * i1);
        *(float4*)(o + 144) = make_float4(a2.x * i2, a2.y * i2, a2.z * i2, a2.w * i2);
        *(float4*)(o + 216) = make_float4(a3.x * i3, a3.y * i3, a3.z * i3, a3.w * i3);
    }
}

// --------------- single-head edge pass (layer 2), 64-thread CTAs -------------
__global__ void __launch_bounds__(64) k_edge1(
    const float* __restrict__ hfeat, const float* __restrict__ ls,
    const float* __restrict__ ld, const float* __restrict__ bias,
    float* __restrict__ outp)
{
    int node = (blockIdx.x * blockDim.x + threadIdx.x) >> 5;
    if (node >= NN) return;
    int lane = threadIdx.x & 31;
    int s0 = g_rowptr[node], s1 = g_rowptr[node + 1];

    float ldv = __ldg(ld + node);
    bool act = (lane < 18);
    float4 acc = make_float4(0.f, 0.f, 0.f, 0.f);
    float  sum = 0.f;

    #pragma unroll 4
    for (int i = s0; i < s1; i++) {
        int s = g_csr[i];
        float v = __ldg(ls + s) + ldv;
        v = fmaxf(v, 0.2f * v);
        float p = __expf(v);
        sum += p;
        if (act) {
            float4 h = __ldg((const float4*)(hfeat + (size_t)s * 72) + lane);
            acc.x += p * h.x; acc.y += p * h.y;
            acc.z += p * h.z; acc.w += p * h.w;
        }
    }

    if (act) {
        float inv = 1.f / fmaxf(sum, 1e-16f);
        int c = lane * 4;
        float4 b = __ldg((const float4*)(bias + c));
        float4 r;
        r.x = acc.x * inv + b.x; r.x = (r.x > 0.f) ? r.x : expm1f(r.x);
        r.y = acc.y * inv + b.y; r.y = (r.y > 0.f) ? r.y : expm1f(r.y);
        r.z = acc.z * inv + b.z; r.z = (r.z > 0.f) ? r.z : expm1f(r.z);
        r.w = acc.w * inv + b.w; r.w = (r.w > 0.f) ? r.w : expm1f(r.w);
        *(float4*)(outp + (size_t)node * 72 + c) = r;
    }
}

// ---- layer-3 edge pass fused with residual + score MLP (final output) -------
__global__ void __launch_bounds__(256) k_edge1f(
    const float* __restrict__ hfeat, const float* __restrict__ ls,
    const float* __restrict__ ld, const float* __restrict__ bias,
    const float* __restrict__ x0,
    const float* __restrict__ Ws1, const float* __restrict__ bs1,
    const float* __restrict__ Ws2, const float* __restrict__ bs2,
    float* __restrict__ out)
{
    __shared__ float w1s[72 * 32];
    __shared__ float w2s[32];
    __shared__ float b1s[32];
    __shared__ float b2s;
    __shared__ __align__(16) float vbuf[8][72];

    for (int i = threadIdx.x; i < 72 * 32; i += 256) w1s[i] = Ws1[i];
    if (threadIdx.x < 32) {
        w2s[threadIdx.x] = Ws2[threadIdx.x];
        b1s[threadIdx.x] = bs1[threadIdx.x];
    }
    if (threadIdx.x == 0) b2s = bs2[0];
    __syncthreads();

    int node = (blockIdx.x * blockDim.x + threadIdx.x) >> 5;
    if (node >= NN) return;
    int lane = threadIdx.x & 31;
    int warp = threadIdx.x >> 5;
    int s0 = g_rowptr[node], s1 = g_rowptr[node + 1];

    float ldv = __ldg(ld + node);
    bool act = (lane < 18);
    float4 acc = make_float4(0.f, 0.f, 0.f, 0.f);
    float  sum = 0.f;

    #pragma unroll 4
    for (int i = s0; i < s1; i++) {
        int s = g_csr[i];
        float v = __ldg(ls + s) + ldv;
        v = fmaxf(v, 0.2f * v);
        float p = __expf(v);
        sum += p;
        if (act) {
            float4 h = __ldg((const float4*)(hfeat + (size_t)s * 72) + lane);
            acc.x += p * h.x; acc.y += p * h.y;
            acc.z += p * h.z; acc.w += p * h.w;
        }
    }

    if (act) {
        float inv = 1.f / fmaxf(sum, 1e-16f);
        int c = lane * 4;
        float4 b = __ldg((const float4*)(bias + c));
        float4 xv = __ldg((const float4*)(x0 + (size_t)node * 72) + lane);
        float4 r;
        r.x = acc.x * inv + b.x; r.x = ((r.x > 0.f) ? r.x : expm1f(r.x)) + xv.x;
        r.y = acc.y * inv + b.y; r.y = ((r.y > 0.f) ? r.y : expm1f(r.y)) + xv.y;
        r.z = acc.z * inv + b.z; r.z = ((r.z > 0.f) ? r.z : expm1f(r.z)) + xv.z;
        r.w = acc.w * inv + b.w; r.w = ((r.w > 0.f) ? r.w : expm1f(r.w)) + xv.w;
        *(float4*)(&vbuf[warp][c]) = r;
    }
    __syncwarp();

    // score MLP: lane j owns hidden unit j
    float t = b1s[lane];
    #pragma unroll 8
    for (int k = 0; k < 72; k++) t += vbuf[warp][k] * w1s[k * 32 + lane];
    float sc = fmaxf(t, 0.f) * w2s[lane];
    #pragma unroll
    for (int o = 16; o > 0; o >>= 1) sc += __shfl_xor_sync(0xffffffffu, sc, o);
    if (lane == 0) out[node] = sc + b2s;
}

// ------------------------------ launch ---------------------------------------
extern "C" void kernel_launch(void* const* d_in, const int* in_sizes, int n_in,
                              void* d_out, int out_size)
{
    const float* x    = (const float*)d_in[0];
    const int*   ei   = (const int*)d_in[1];
    const float* W_in = (const float*)d_in[2];
    const float* b_in = (const float*)d_in[3];
    const float* W1   = (const float*)d_in[4];
    const float* as1  = (const float*)d_in[5];
    const float* ad1  = (const float*)d_in[6];
    const float* b1   = (const float*)d_in[7];
    const float* W2   = (const float*)d_in[8];
    const float* as2  = (const float*)d_in[9];
    const float* ad2  = (const float*)d_in[10];
    const float* b2   = (const float*)d_in[11];
    const float* W3   = (const float*)d_in[12];
    const float* as3  = (const float*)d_in[13];
    const float* ad3  = (const float*)d_in[14];
    const float* b3   = (const float*)d_in[15];
    const float* Ws1  = (const float*)d_in[16];
    const float* bs1  = (const float*)d_in[17];
    const float* Ws2  = (const float*)d_in[18];
    const float* bs2  = (const float*)d_in[19];
    float* out = (float*)d_out;

    float *px0, *pagg, *po1, *ph2, *po2, *ph3;
    float *pls1, *pld1, *pls2, *pld2, *pls3, *pld3;
    int* prowptr;
    __nv_bfloat16 *pw0h, *pw0l, *pw1h, *pw1l, *pw2h, *pw2l, *pw3h, *pw3l;
    cudaGetSymbolAddress((void**)&px0,  g_x0);
    cudaGetSymbolAddress((void**)&pagg, g_agg);
    cudaGetSymbolAddress((void**)&po1,  g_o1);
    cudaGetSymbolAddress((void**)&ph2,  g_h2);
    cudaGetSymbolAddress((void**)&po2,  g_o2);
    cudaGetSymbolAddress((void**)&ph3,  g_h3);
    cudaGetSymbolAddress((void**)&pls1, g_ls1);
    cudaGetSymbolAddress((void**)&pld1, g_ld1);
    cudaGetSymbolAddress((void**)&pls2, g_ls2);
    cudaGetSymbolAddress((void**)&pld2, g_ld2);
    cudaGetSymbolAddress((void**)&pls3, g_ls3);
    cudaGetSymbolAddress((void**)&pld3, g_ld3);
    cudaGetSymbolAddress((void**)&prowptr, g_rowptr);
    cudaGetSymbolAddress((void**)&pw0h, g_w0h);
    cudaGetSymbolAddress((void**)&pw0l, g_w0l);
    cudaGetSymbolAddress((void**)&pw1h, g_w1h);
    cudaGetSymbolAddress((void**)&pw1l, g_w1l);
    cudaGetSymbolAddress((void**)&pw2h, g_w2h);
    cudaGetSymbolAddress((void**)&pw2l, g_w2l);
    cudaGetSymbolAddress((void**)&pw3h, g_w3h);
    cudaGetSymbolAddress((void**)&pw3l, g_w3l);

    // side stream + fork/join events (capture-safe: branches recorded into graph)
    cudaStream_t side;
    cudaStreamCreateWithFlags(&side, cudaStreamNonBlocking);
    cudaEvent_t eFork, eJoin;
    cudaEventCreateWithFlags(&eFork, cudaEventDisableTiming);
    cudaEventCreateWithFlags(&eJoin, cudaEventDisableTiming);

    // fork: CSR build runs concurrently with layer-0 compute
    cudaEventRecord(eFork, 0);
    cudaStreamWaitEvent(side, eFork, 0);

    // --- side branch: CSR build ---
    cudaMemsetAsync(prowptr, 0, (NN + 1) * sizeof(int), side);
    k_count_deg<<<(EE + 255) / 256, 256, 0, side>>>(ei);
    k_scan_blk<<<NBLK, 256, 0, side>>>();
    k_scan_top<<<1, 256, 0, side>>>();
    k_add_self<<<(NN + 255) / 256, 256, 0, side>>>();
    k_scatter<<<(EE + 255) / 256, 256, 0, side>>>(ei);
    cudaEventRecord(eJoin, side);

    // --- main branch: prep + layer-0 GEMM + layer-1 logits ---
    k_prep<<<(74304 + 255) / 256, 256>>>(W_in, W1, W2, W3, as1, ad1);
    k_mmagemm<<<dim3(391, 1), 384>>>(x, 256, 0, pw0h, pw0l, b_in, px0,
                                     nullptr, nullptr, nullptr, nullptr, 1,
                                     NN, 256, 72, 1, 0);
    k_logits8<<<(NN + 255) / 256, 256>>>(px0, pls1, pld1);

    // join: edge aggregation needs both CSR and logits
    cudaStreamWaitEvent(0, eJoin, 0);

    // --- layer 1 ---
    k_edge4agg<<<(NN * 32) / 64, 64>>>(px0, pls1, pld1, pagg);
    k_mmagemm<<<dim3(391, 4), 384>>>(pagg, 288, 1, pw1h, pw1l, b1, po1,
                                     nullptr, nullptr, nullptr, nullptr, 1,
                                     NN, 72, 288, 1, 1);

    // --- layer 2 ---
    k_mmagemm<<<dim3(391, 1), 384>>>(po1, 288, 0, pw2h, pw2l, nullptr, ph2,
                                     as2, ad2, pls2, pld2, 1,
                                     NN, 288, 72, 0, 0);
    k_edge1<<<(NN * 32) / 64, 64>>>(ph2, pls2, pld2, b2, po2);

    // --- layer 3 ---
    k_mmagemm<<<dim3(391, 1), 384>>>(po2, 72, 0, pw3h, pw3l, nullptr, ph3,
                                     as3, ad3, pls3, pld3, 1,
                                     NN, 72, 72, 0, 0);
    k_edge1f<<<(NN * 32) / 256, 256>>>(ph3, pls3, pld3, b3, px0,
                                       Ws1, bs1, Ws2, bs2, out);
}